// round 1
// baseline (speedup 1.0000x reference)
#include <cuda_runtime.h>
#include <cstdint>

#define NTOK  32768          // B*S
#define HDIM  512
#define IDIM  1024
#define NEXP  8
#define NSLOT (2*NTOK)       // top-2 -> 2 slots per token, slot = 2*t + k
#define RBLOCKS (NTOK/8)     // router blocks (8 tokens/block)

// ---------------- device scratch (allocation-free rule: __device__ globals) ----
__device__ int   g_cnt[NEXP];                       // tokens per expert (zeroed each call)
__device__ int   g_list[NEXP*NTOK];                 // slot ids, grouped by expert
__device__ float g_wt[NSLOT];                       // combine weight per slot
__device__ float g_psum[RBLOCKS*NEXP];              // per-block softmax-prob partials
__device__ float g_act[(long long)NSLOT*IDIM];      // silu(g)*u rows, 256 MB
__device__ float g_eo [(long long)NSLOT*HDIM];      // per-slot expert output, 128 MB

// ---------------- 0: zero counters (graph replays need fresh state) ------------
__global__ void init_kernel() {
    if (threadIdx.x < NEXP) g_cnt[threadIdx.x] = 0;
}

// ---------------- 1: router ----------------------------------------------------
__global__ void __launch_bounds__(256) router_kernel(const float* __restrict__ hs,
                                                     const float* __restrict__ wr) {
    __shared__ float swr[NEXP*HDIM];     // 16 KB router weights
    __shared__ float sprob[8][NEXP];
    int tid = threadIdx.x;
    for (int i = tid; i < NEXP*HDIM; i += 256) swr[i] = wr[i];
    __syncthreads();

    int warp = tid >> 5, lane = tid & 31;
    int t = blockIdx.x * 8 + warp;
    const float* hrow = hs + (size_t)t * HDIM;

    float acc[NEXP];
#pragma unroll
    for (int e = 0; e < NEXP; e++) acc[e] = 0.f;
    for (int j = lane; j < HDIM; j += 32) {
        float hv = hrow[j];
#pragma unroll
        for (int e = 0; e < NEXP; e++) acc[e] = fmaf(hv, swr[e*HDIM + j], acc[e]);
    }
#pragma unroll
    for (int e = 0; e < NEXP; e++) {
#pragma unroll
        for (int o = 16; o > 0; o >>= 1) acc[e] += __shfl_xor_sync(0xffffffffu, acc[e], o);
    }

    if (lane == 0) {
        // top-2, ties -> lowest index (matches jax.lax.top_k)
        int e0 = 0; float v0 = acc[0];
#pragma unroll
        for (int e = 1; e < NEXP; e++) if (acc[e] > v0) { v0 = acc[e]; e0 = e; }
        int e1 = -1; float v1 = -1e30f;
#pragma unroll
        for (int e = 0; e < NEXP; e++) if (e != e0 && acc[e] > v1) { v1 = acc[e]; e1 = e; }

        float z  = __expf(v1 - v0);          // v1 <= v0, stable
        float p1 = z / (1.f + z);
        g_wt[2*t]     = 1.f - p1;
        g_wt[2*t + 1] = p1;

        int pos0 = atomicAdd(&g_cnt[e0], 1);
        g_list[e0*NTOK + pos0] = 2*t;
        int pos1 = atomicAdd(&g_cnt[e1], 1);
        g_list[e1*NTOK + pos1] = 2*t + 1;

        // full-E softmax probs for aux loss
        float s = 0.f, pe[NEXP];
#pragma unroll
        for (int e = 0; e < NEXP; e++) { pe[e] = __expf(acc[e] - v0); s += pe[e]; }
        float inv = 1.f / s;
#pragma unroll
        for (int e = 0; e < NEXP; e++) sprob[warp][e] = pe[e] * inv;
    }
    __syncthreads();
    if (tid < NEXP) {
        float s = 0.f;
#pragma unroll
        for (int w = 0; w < 8; w++) s += sprob[w][tid];
        g_psum[blockIdx.x*NEXP + tid] = s;   // fixed-order partial -> deterministic aux
    }
}

// ---------------- 2: aux loss (deterministic fixed-order reduction) ------------
__global__ void aux_kernel(float* __restrict__ out, int out_size) {
    __shared__ float part[256];
    int tid = threadIdx.x;
    int e = tid & 7, c = tid >> 3;                   // 32 chunks x 8 experts
    const int CH = RBLOCKS / 32;
    float s = 0.f;
    for (int b = c*CH; b < (c+1)*CH; b++) s += g_psum[b*NEXP + e];
    part[tid] = s;
    __syncthreads();
    if (tid < NEXP) {
        float tot = 0.f;
        for (int cc = 0; cc < 32; cc++) tot += part[cc*8 + tid];   // reads column tid only
        part[tid] = (tot / (float)NTOK) * ((float)g_cnt[tid] / (float)NSLOT) * (float)NEXP;
    }
    __syncthreads();
    if (tid == 0 && out_size > NTOK*HDIM) {
        float a = 0.f;
#pragma unroll
        for (int ee = 0; ee < NEXP; ee++) a += part[ee];
        out[(size_t)NTOK*HDIM] = a;
    }
}

// ---------------- 3: gate/up GEMM + silu  (per expert, gathered rows) ----------
// C tile 128 tokens x 64 chans, BK=16, 256 thr, 8x4 microtile, two B matrices.
__global__ void __launch_bounds__(256, 2) gateup_kernel(const float* __restrict__ hs,
                                                        const float* __restrict__ wg,
                                                        const float* __restrict__ wu) {
    int e   = blockIdx.z;
    int cnt = g_cnt[e];
    int p0  = blockIdx.y * 128;
    if (p0 >= cnt) return;
    int i0  = blockIdx.x * 64;

    __shared__ float As[16][128];
    __shared__ float Bg[16][64];
    __shared__ float Bu[16][64];

    int tid = threadIdx.x;
    // A loader: row = tid&127, loads k-vecs (ac) and (ac+2)
    int ar = tid & 127, ac = tid >> 7;
    int pa = p0 + ar;
    int cl = (pa < cnt) ? pa : (cnt - 1);
    int toka = g_list[e*NTOK + cl] >> 1;
    const float* arow = hs + (size_t)toka * HDIM;
    // B loader: chan = tid>>2, k-vec = tid&3
    int bn = tid >> 2, bc = tid & 3;
    const float* bgrow = wg + ((size_t)e*IDIM + i0 + bn) * HDIM;
    const float* burow = wu + ((size_t)e*IDIM + i0 + bn) * HDIM;

    int tx = tid & 15, ty = tid >> 4;    // col=tx*4, rows=ty*8..+7
    float accg[8][4], accu[8][4];
#pragma unroll
    for (int r = 0; r < 8; r++)
#pragma unroll
        for (int c = 0; c < 4; c++) { accg[r][c] = 0.f; accu[r][c] = 0.f; }

    for (int k0 = 0; k0 < HDIM; k0 += 16) {
        float4 a0 = *(const float4*)(arow  + k0 + ac*4);
        float4 a1 = *(const float4*)(arow  + k0 + (ac+2)*4);
        float4 gv = *(const float4*)(bgrow + k0 + bc*4);
        float4 uv = *(const float4*)(burow + k0 + bc*4);
        __syncthreads();
        As[ac*4+0][ar] = a0.x; As[ac*4+1][ar] = a0.y; As[ac*4+2][ar] = a0.z; As[ac*4+3][ar] = a0.w;
        As[(ac+2)*4+0][ar] = a1.x; As[(ac+2)*4+1][ar] = a1.y; As[(ac+2)*4+2][ar] = a1.z; As[(ac+2)*4+3][ar] = a1.w;
        Bg[bc*4+0][bn] = gv.x; Bg[bc*4+1][bn] = gv.y; Bg[bc*4+2][bn] = gv.z; Bg[bc*4+3][bn] = gv.w;
        Bu[bc*4+0][bn] = uv.x; Bu[bc*4+1][bn] = uv.y; Bu[bc*4+2][bn] = uv.z; Bu[bc*4+3][bn] = uv.w;
        __syncthreads();
#pragma unroll
        for (int k = 0; k < 16; k++) {
            float4 f0 = *(const float4*)&As[k][ty*8];
            float4 f1 = *(const float4*)&As[k][ty*8 + 4];
            float4 g4 = *(const float4*)&Bg[k][tx*4];
            float4 u4 = *(const float4*)&Bu[k][tx*4];
            float av[8]  = {f0.x,f0.y,f0.z,f0.w,f1.x,f1.y,f1.z,f1.w};
            float bgv[4] = {g4.x,g4.y,g4.z,g4.w};
            float buv[4] = {u4.x,u4.y,u4.z,u4.w};
#pragma unroll
            for (int r = 0; r < 8; r++)
#pragma unroll
                for (int c = 0; c < 4; c++) {
                    accg[r][c] = fmaf(av[r], bgv[c], accg[r][c]);
                    accu[r][c] = fmaf(av[r], buv[c], accu[r][c]);
                }
        }
    }
    // epilogue: act = silu(g)*u -> scratch row keyed by slot
#pragma unroll
    for (int r = 0; r < 8; r++) {
        int p = p0 + ty*8 + r;
        if (p < cnt) {
            int slot = g_list[e*NTOK + p];
            float4 o;
            float g, sg;
            g = accg[r][0]; sg = g / (1.f + __expf(-g)); o.x = sg * accu[r][0];
            g = accg[r][1]; sg = g / (1.f + __expf(-g)); o.y = sg * accu[r][1];
            g = accg[r][2]; sg = g / (1.f + __expf(-g)); o.z = sg * accu[r][2];
            g = accg[r][3]; sg = g / (1.f + __expf(-g)); o.w = sg * accu[r][3];
            *(float4*)&g_act[(size_t)slot*IDIM + i0 + tx*4] = o;
        }
    }
}

// ---------------- 4: down GEMM  (act @ w_down^T per expert) --------------------
// C tile 128 slots x 128 h, BK=16, 256 thr, 8x8 microtile.
__global__ void __launch_bounds__(256, 2) down_kernel(const float* __restrict__ wd) {
    int e   = blockIdx.z;
    int cnt = g_cnt[e];
    int p0  = blockIdx.y * 128;
    if (p0 >= cnt) return;
    int h0  = blockIdx.x * 128;

    __shared__ float As[16][128];
    __shared__ float Bs[16][128];

    int tid = threadIdx.x;
    int r_ = tid & 127, c_ = tid >> 7;
    int pa = p0 + r_;
    int cl = (pa < cnt) ? pa : (cnt - 1);
    int slota = g_list[e*NTOK + cl];
    const float* arow = g_act + (size_t)slota * IDIM;
    const float* brow = wd + ((size_t)e*HDIM + h0 + r_) * IDIM;

    int tx = tid & 15, ty = tid >> 4;    // cols=tx*8..+7, rows=ty*8..+7
    float acc[8][8];
#pragma unroll
    for (int r = 0; r < 8; r++)
#pragma unroll
        for (int c = 0; c < 8; c++) acc[r][c] = 0.f;

    for (int k0 = 0; k0 < IDIM; k0 += 16) {
        float4 a0 = *(const float4*)(arow + k0 + c_*4);
        float4 a1 = *(const float4*)(arow + k0 + (c_+2)*4);
        float4 b0 = *(const float4*)(brow + k0 + c_*4);
        float4 b1 = *(const float4*)(brow + k0 + (c_+2)*4);
        __syncthreads();
        As[c_*4+0][r_] = a0.x; As[c_*4+1][r_] = a0.y; As[c_*4+2][r_] = a0.z; As[c_*4+3][r_] = a0.w;
        As[(c_+2)*4+0][r_] = a1.x; As[(c_+2)*4+1][r_] = a1.y; As[(c_+2)*4+2][r_] = a1.z; As[(c_+2)*4+3][r_] = a1.w;
        Bs[c_*4+0][r_] = b0.x; Bs[c_*4+1][r_] = b0.y; Bs[c_*4+2][r_] = b0.z; Bs[c_*4+3][r_] = b0.w;
        Bs[(c_+2)*4+0][r_] = b1.x; Bs[(c_+2)*4+1][r_] = b1.y; Bs[(c_+2)*4+2][r_] = b1.z; Bs[(c_+2)*4+3][r_] = b1.w;
        __syncthreads();
#pragma unroll
        for (int k = 0; k < 16; k++) {
            float4 f0 = *(const float4*)&As[k][ty*8];
            float4 f1 = *(const float4*)&As[k][ty*8 + 4];
            float4 g0 = *(const float4*)&Bs[k][tx*8];
            float4 g1 = *(const float4*)&Bs[k][tx*8 + 4];
            float av[8] = {f0.x,f0.y,f0.z,f0.w,f1.x,f1.y,f1.z,f1.w};
            float bv[8] = {g0.x,g0.y,g0.z,g0.w,g1.x,g1.y,g1.z,g1.w};
#pragma unroll
            for (int r = 0; r < 8; r++)
#pragma unroll
                for (int c = 0; c < 8; c++)
                    acc[r][c] = fmaf(av[r], bv[c], acc[r][c]);
        }
    }
#pragma unroll
    for (int r = 0; r < 8; r++) {
        int p = p0 + ty*8 + r;
        if (p < cnt) {
            int slot = g_list[e*NTOK + p];
            float* orow = &g_eo[(size_t)slot*HDIM + h0 + tx*8];
            float4 o0 = {acc[r][0], acc[r][1], acc[r][2], acc[r][3]};
            float4 o1 = {acc[r][4], acc[r][5], acc[r][6], acc[r][7]};
            *(float4*)(orow)     = o0;
            *(float4*)(orow + 4) = o1;
        }
    }
}

// ---------------- 5: combine (out = w0*eo[2t] + w1*eo[2t+1]) -------------------
__global__ void combine_kernel(float* __restrict__ out) {
    int idx = blockIdx.x * 256 + threadIdx.x;          // float4 index
    const int TOTAL = NTOK * HDIM / 4;
    if (idx >= TOTAL) return;
    int t  = idx / (HDIM/4);
    int h4 = idx - t * (HDIM/4);
    float w0 = g_wt[2*t], w1 = g_wt[2*t + 1];
    float4 x0 = *(const float4*)&g_eo[(size_t)(2*t)  *HDIM + h4*4];
    float4 x1 = *(const float4*)&g_eo[(size_t)(2*t+1)*HDIM + h4*4];
    float4 o;
    o.x = w0*x0.x + w1*x1.x;
    o.y = w0*x0.y + w1*x1.y;
    o.z = w0*x0.z + w1*x1.z;
    o.w = w0*x0.w + w1*x1.w;
    ((float4*)out)[idx] = o;
}

// ---------------- launch -------------------------------------------------------
extern "C" void kernel_launch(void* const* d_in, const int* in_sizes, int n_in,
                              void* d_out, int out_size) {
    const float* hs = (const float*)d_in[0];   // hidden_states [B,S,H]
    const float* wr = (const float*)d_in[1];   // w_router [E,H]
    const float* wg = (const float*)d_in[2];   // w_gate [E,I,H]
    const float* wu = (const float*)d_in[3];   // w_up   [E,I,H]
    const float* wd = (const float*)d_in[4];   // w_down [E,H,I]
    float* out = (float*)d_out;

    init_kernel<<<1, 32>>>();
    router_kernel<<<RBLOCKS, 256>>>(hs, wr);
    aux_kernel<<<1, 256>>>(out, out_size);
    gateup_kernel<<<dim3(IDIM/64, NTOK/128, NEXP), 256>>>(hs, wg, wu);
    down_kernel<<<dim3(HDIM/128, NTOK/128, NEXP), 256>>>(wd);
    combine_kernel<<<(NTOK*HDIM/4 + 255)/256, 256>>>(out);
}

// round 4
// speedup vs baseline: 1.7084x; 1.7084x over previous
#include <cuda_runtime.h>
#include <cuda_bf16.h>
#include <cstdint>

#define NTOK  32768          // B*S
#define HDIM  512
#define IDIM  1024
#define NEXP  8
#define NSLOT (2*NTOK)
#define RBLOCKS (NTOK/8)

// ======================= device scratch ======================================
__device__ int   g_cnt[NEXP];
__device__ int   g_list[NEXP*NTOK];
__device__ float g_wt[NSLOT];
__device__ float g_psum[RBLOCKS*NEXP];
__device__ __nv_bfloat16 g_hs_hi[NTOK*HDIM];
__device__ __nv_bfloat16 g_hs_lo[NTOK*HDIM];
__device__ __nv_bfloat16 g_wg_hi[NEXP*IDIM*HDIM];
__device__ __nv_bfloat16 g_wg_lo[NEXP*IDIM*HDIM];
__device__ __nv_bfloat16 g_wu_hi[NEXP*IDIM*HDIM];
__device__ __nv_bfloat16 g_wu_lo[NEXP*IDIM*HDIM];
__device__ __nv_bfloat16 g_wd_hi[NEXP*HDIM*IDIM];
__device__ __nv_bfloat16 g_wd_lo[NEXP*HDIM*IDIM];
__device__ __nv_bfloat16 g_act_hi[67108864];   // NSLOT*IDIM
__device__ __nv_bfloat16 g_act_lo[67108864];
__device__ float g_eo[(size_t)NSLOT*HDIM];

// ======================= mma.sync helper =====================================
__device__ __forceinline__ void mma16816(float* c, uint32_t a0, uint32_t a1,
                                         uint32_t a2, uint32_t a3,
                                         uint32_t b0, uint32_t b1) {
    asm volatile(
        "mma.sync.aligned.m16n8k16.row.col.f32.bf16.bf16.f32 "
        "{%0,%1,%2,%3}, {%4,%5,%6,%7}, {%8,%9}, {%0,%1,%2,%3};"
        : "+f"(c[0]), "+f"(c[1]), "+f"(c[2]), "+f"(c[3])
        : "r"(a0), "r"(a1), "r"(a2), "r"(a3), "r"(b0), "r"(b1));
}
__device__ __forceinline__ uint32_t lds32(const __nv_bfloat16* p) {
    return *(const uint32_t*)p;
}

// ======================= 0: init =============================================
__global__ void init_kernel() {
    if (threadIdx.x < NEXP) g_cnt[threadIdx.x] = 0;
}

// ======================= 1: split fp32 -> bf16 hi/lo =========================
// which: 0=hs, 1=wg, 2=wu, 3=wd.  Destination pointers resolved in DEVICE code
// (host-side &__device__global is not a device address — R3 bug).
__global__ void __launch_bounds__(256) split_kernel(const float* __restrict__ src,
                                                    int which, int n4) {
    int i = blockIdx.x * 256 + threadIdx.x;
    if (i >= n4) return;
    __nv_bfloat16* hi;
    __nv_bfloat16* lo;
    switch (which) {
        case 0:  hi = g_hs_hi; lo = g_hs_lo; break;
        case 1:  hi = g_wg_hi; lo = g_wg_lo; break;
        case 2:  hi = g_wu_hi; lo = g_wu_lo; break;
        default: hi = g_wd_hi; lo = g_wd_lo; break;
    }
    float4 v = ((const float4*)src)[i];
    __nv_bfloat16 h0 = __float2bfloat16(v.x), h1 = __float2bfloat16(v.y);
    __nv_bfloat16 h2 = __float2bfloat16(v.z), h3 = __float2bfloat16(v.w);
    __nv_bfloat16 l0 = __float2bfloat16(v.x - __bfloat162float(h0));
    __nv_bfloat16 l1 = __float2bfloat16(v.y - __bfloat162float(h1));
    __nv_bfloat16 l2 = __float2bfloat16(v.z - __bfloat162float(h2));
    __nv_bfloat16 l3 = __float2bfloat16(v.w - __bfloat162float(h3));
    __nv_bfloat162 hp0; hp0.x = h0; hp0.y = h1;
    __nv_bfloat162 hp1; hp1.x = h2; hp1.y = h3;
    __nv_bfloat162 lp0; lp0.x = l0; lp0.y = l1;
    __nv_bfloat162 lp1; lp1.x = l2; lp1.y = l3;
    ((uint2*)hi)[i] = make_uint2(*(uint32_t*)&hp0, *(uint32_t*)&hp1);
    ((uint2*)lo)[i] = make_uint2(*(uint32_t*)&lp0, *(uint32_t*)&lp1);
}

// ======================= 2: router ===========================================
__global__ void __launch_bounds__(256) router_kernel(const float* __restrict__ hs,
                                                     const float* __restrict__ wr) {
    __shared__ float swr[NEXP*HDIM];
    __shared__ float sprob[8][NEXP];
    int tid = threadIdx.x;
    for (int i = tid; i < NEXP*HDIM; i += 256) swr[i] = wr[i];
    __syncthreads();

    int warp = tid >> 5, lane = tid & 31;
    int t = blockIdx.x * 8 + warp;
    const float* hrow = hs + (size_t)t * HDIM;

    float acc[NEXP];
#pragma unroll
    for (int e = 0; e < NEXP; e++) acc[e] = 0.f;
    for (int j = lane; j < HDIM; j += 32) {
        float hv = hrow[j];
#pragma unroll
        for (int e = 0; e < NEXP; e++) acc[e] = fmaf(hv, swr[e*HDIM + j], acc[e]);
    }
#pragma unroll
    for (int e = 0; e < NEXP; e++) {
#pragma unroll
        for (int o = 16; o > 0; o >>= 1) acc[e] += __shfl_xor_sync(0xffffffffu, acc[e], o);
    }

    if (lane == 0) {
        int e0 = 0; float v0 = acc[0];
#pragma unroll
        for (int e = 1; e < NEXP; e++) if (acc[e] > v0) { v0 = acc[e]; e0 = e; }
        int e1 = -1; float v1 = -1e30f;
#pragma unroll
        for (int e = 0; e < NEXP; e++) if (e != e0 && acc[e] > v1) { v1 = acc[e]; e1 = e; }

        float z  = __expf(v1 - v0);
        float p1 = z / (1.f + z);
        g_wt[2*t]     = 1.f - p1;
        g_wt[2*t + 1] = p1;

        int pos0 = atomicAdd(&g_cnt[e0], 1);
        g_list[e0*NTOK + pos0] = 2*t;
        int pos1 = atomicAdd(&g_cnt[e1], 1);
        g_list[e1*NTOK + pos1] = 2*t + 1;

        float s = 0.f, pe[NEXP];
#pragma unroll
        for (int e = 0; e < NEXP; e++) { pe[e] = __expf(acc[e] - v0); s += pe[e]; }
        float inv = 1.f / s;
#pragma unroll
        for (int e = 0; e < NEXP; e++) sprob[warp][e] = pe[e] * inv;
    }
    __syncthreads();
    if (tid < NEXP) {
        float s = 0.f;
#pragma unroll
        for (int w = 0; w < 8; w++) s += sprob[w][tid];
        g_psum[blockIdx.x*NEXP + tid] = s;
    }
}

// ======================= 3: aux loss =========================================
__global__ void aux_kernel(float* __restrict__ out, int out_size) {
    __shared__ float part[256];
    int tid = threadIdx.x;
    int e = tid & 7, c = tid >> 3;
    const int CH = RBLOCKS / 32;
    float s = 0.f;
    for (int b = c*CH; b < (c+1)*CH; b++) s += g_psum[b*NEXP + e];
    part[tid] = s;
    __syncthreads();
    if (tid < NEXP) {
        float tot = 0.f;
        for (int cc = 0; cc < 32; cc++) tot += part[cc*8 + tid];
        part[tid] = (tot / (float)NTOK) * ((float)g_cnt[tid] / (float)NSLOT) * (float)NEXP;
    }
    __syncthreads();
    if (tid == 0 && out_size > NTOK*HDIM) {
        float a = 0.f;
#pragma unroll
        for (int ee = 0; ee < NEXP; ee++) a += part[ee];
        out[(size_t)NTOK*HDIM] = a;
    }
}

// ======================= 4: gate/up mma.sync GEMM ============================
// CTA: 128 tokens x 32 I, 4 warps (each 32 rows x 32 cols, g AND u).
// K=512 in 64-chunks, padded smem stride 72, 3-term bf16 split.
#define LDP 72
#define GU_A   (128*LDP)            // elems per A array
#define GU_B   (32*LDP)
#define GU_SMEM_BYTES ((2*GU_A + 4*GU_B)*2 + 1024)
__global__ void __launch_bounds__(128) gateup_mma_kernel() {
    int e   = blockIdx.z;
    int cnt = g_cnt[e];
    int p0  = blockIdx.y * 128;
    if (p0 >= cnt) return;
    int i0  = blockIdx.x * 32;

    extern __shared__ char smem_raw[];
    __nv_bfloat16* s_ahi = (__nv_bfloat16*)smem_raw;
    __nv_bfloat16* s_alo = s_ahi + GU_A;
    __nv_bfloat16* s_bgh = s_alo + GU_A;
    __nv_bfloat16* s_bgl = s_bgh + GU_B;
    __nv_bfloat16* s_buh = s_bgl + GU_B;
    __nv_bfloat16* s_bul = s_buh + GU_B;
    int* s_rowoff = (int*)(s_bul + GU_B);
    int* s_slot   = s_rowoff + 128;

    int tid = threadIdx.x, wid = tid >> 5, lane = tid & 31;
    int g_ = lane >> 2, t_ = lane & 3;

    {
        int p = p0 + tid;
        int cl = (p < cnt) ? p : (cnt - 1);
        int sl = g_list[e*NTOK + cl];
        s_rowoff[tid] = (sl >> 1) * HDIM;
        s_slot[tid]   = (p < cnt) ? sl : -1;
    }
    __syncthreads();

    float cg[2][4][4], cu[2][4][4];
#pragma unroll
    for (int m = 0; m < 2; m++)
#pragma unroll
        for (int n = 0; n < 4; n++)
#pragma unroll
            for (int q = 0; q < 4; q++) { cg[m][n][q] = 0.f; cu[m][n][q] = 0.f; }

    int rm = wid * 32;
    for (int c = 0; c < 8; c++) {
        int k0 = c * 64;
        // load A (128 rows x 64 k) hi+lo
        for (int idx = tid; idx < 1024; idx += 128) {
            int row = idx >> 3, v = idx & 7;
            int off = s_rowoff[row] + k0 + v*8;
            *(uint4*)(s_ahi + row*LDP + v*8) = *(const uint4*)(g_hs_hi + off);
            *(uint4*)(s_alo + row*LDP + v*8) = *(const uint4*)(g_hs_lo + off);
        }
        // load B (32 rows x 64 k) x4 arrays
        for (int idx = tid; idx < 256; idx += 128) {
            int row = idx >> 3, v = idx & 7;
            size_t off = ((size_t)e*IDIM + i0 + row) * HDIM + k0 + v*8;
            *(uint4*)(s_bgh + row*LDP + v*8) = *(const uint4*)(g_wg_hi + off);
            *(uint4*)(s_bgl + row*LDP + v*8) = *(const uint4*)(g_wg_lo + off);
            *(uint4*)(s_buh + row*LDP + v*8) = *(const uint4*)(g_wu_hi + off);
            *(uint4*)(s_bul + row*LDP + v*8) = *(const uint4*)(g_wu_lo + off);
        }
        __syncthreads();
#pragma unroll
        for (int kk = 0; kk < 64; kk += 16) {
            uint32_t ah[2][4], al[2][4];
#pragma unroll
            for (int m = 0; m < 2; m++) {
                int r0 = (rm + m*16 + g_)*LDP + kk + t_*2;
                int r1 = (rm + m*16 + g_ + 8)*LDP + kk + t_*2;
                ah[m][0] = lds32(s_ahi + r0);     ah[m][1] = lds32(s_ahi + r1);
                ah[m][2] = lds32(s_ahi + r0 + 8); ah[m][3] = lds32(s_ahi + r1 + 8);
                al[m][0] = lds32(s_alo + r0);     al[m][1] = lds32(s_alo + r1);
                al[m][2] = lds32(s_alo + r0 + 8); al[m][3] = lds32(s_alo + r1 + 8);
            }
#pragma unroll
            for (int n = 0; n < 4; n++) {
                int b0o = (n*8 + g_)*LDP + kk + t_*2;
                uint32_t gh0 = lds32(s_bgh + b0o), gh1 = lds32(s_bgh + b0o + 8);
                uint32_t gl0 = lds32(s_bgl + b0o), gl1 = lds32(s_bgl + b0o + 8);
                uint32_t uh0 = lds32(s_buh + b0o), uh1 = lds32(s_buh + b0o + 8);
                uint32_t ul0 = lds32(s_bul + b0o), ul1 = lds32(s_bul + b0o + 8);
#pragma unroll
                for (int m = 0; m < 2; m++) {
                    mma16816(cg[m][n], ah[m][0],ah[m][1],ah[m][2],ah[m][3], gh0, gh1);
                    mma16816(cg[m][n], ah[m][0],ah[m][1],ah[m][2],ah[m][3], gl0, gl1);
                    mma16816(cg[m][n], al[m][0],al[m][1],al[m][2],al[m][3], gh0, gh1);
                    mma16816(cu[m][n], ah[m][0],ah[m][1],ah[m][2],ah[m][3], uh0, uh1);
                    mma16816(cu[m][n], ah[m][0],ah[m][1],ah[m][2],ah[m][3], ul0, ul1);
                    mma16816(cu[m][n], al[m][0],al[m][1],al[m][2],al[m][3], uh0, uh1);
                }
            }
        }
        __syncthreads();
    }

    // epilogue: act = silu(g)*u -> bf16 hi/lo by slot
#pragma unroll
    for (int m = 0; m < 2; m++) {
#pragma unroll
        for (int half = 0; half < 2; half++) {
            int lr = rm + m*16 + g_ + half*8;
            int slot = s_slot[lr];
            if (slot < 0) continue;
            __nv_bfloat16* oh = g_act_hi + (size_t)slot * IDIM + i0;
            __nv_bfloat16* ol = g_act_lo + (size_t)slot * IDIM + i0;
#pragma unroll
            for (int n = 0; n < 4; n++) {
                float gv0 = cg[m][n][2*half],   uv0 = cu[m][n][2*half];
                float gv1 = cg[m][n][2*half+1], uv1 = cu[m][n][2*half+1];
                float a0 = (gv0 / (1.f + __expf(-gv0))) * uv0;
                float a1 = (gv1 / (1.f + __expf(-gv1))) * uv1;
                __nv_bfloat16 h0 = __float2bfloat16(a0);
                __nv_bfloat16 h1 = __float2bfloat16(a1);
                __nv_bfloat16 l0 = __float2bfloat16(a0 - __bfloat162float(h0));
                __nv_bfloat16 l1 = __float2bfloat16(a1 - __bfloat162float(h1));
                __nv_bfloat162 hp; hp.x = h0; hp.y = h1;
                __nv_bfloat162 lp; lp.x = l0; lp.y = l1;
                *(uint32_t*)(oh + n*8 + t_*2) = *(uint32_t*)&hp;
                *(uint32_t*)(ol + n*8 + t_*2) = *(uint32_t*)&lp;
            }
        }
    }
}

// ======================= 5: down mma.sync GEMM ===============================
// CTA: 128 slots x 64 h, 4 warps (each 32 rows x 64 cols). K=1024 in 64-chunks.
#define DN_A   (128*LDP)
#define DN_B   (64*LDP)
#define DN_SMEM_BYTES ((2*DN_A + 2*DN_B)*2 + 1024)
__global__ void __launch_bounds__(128) down_mma_kernel() {
    int e   = blockIdx.z;
    int cnt = g_cnt[e];
    int p0  = blockIdx.y * 128;
    if (p0 >= cnt) return;
    int h0  = blockIdx.x * 64;

    extern __shared__ char smem_raw[];
    __nv_bfloat16* s_ahi = (__nv_bfloat16*)smem_raw;
    __nv_bfloat16* s_alo = s_ahi + DN_A;
    __nv_bfloat16* s_bh  = s_alo + DN_A;
    __nv_bfloat16* s_bl  = s_bh + DN_B;
    int* s_rowoff = (int*)(s_bl + DN_B);
    int* s_slot   = s_rowoff + 128;

    int tid = threadIdx.x, wid = tid >> 5, lane = tid & 31;
    int g_ = lane >> 2, t_ = lane & 3;

    {
        int p = p0 + tid;
        int cl = (p < cnt) ? p : (cnt - 1);
        int sl = g_list[e*NTOK + cl];
        s_rowoff[tid] = sl * IDIM;
        s_slot[tid]   = (p < cnt) ? sl : -1;
    }
    __syncthreads();

    float cd[2][8][4];
#pragma unroll
    for (int m = 0; m < 2; m++)
#pragma unroll
        for (int n = 0; n < 8; n++)
#pragma unroll
            for (int q = 0; q < 4; q++) cd[m][n][q] = 0.f;

    int rm = wid * 32;
    for (int c = 0; c < 16; c++) {
        int k0 = c * 64;
        for (int idx = tid; idx < 1024; idx += 128) {
            int row = idx >> 3, v = idx & 7;
            int off = s_rowoff[row] + k0 + v*8;
            *(uint4*)(s_ahi + row*LDP + v*8) = *(const uint4*)(g_act_hi + off);
            *(uint4*)(s_alo + row*LDP + v*8) = *(const uint4*)(g_act_lo + off);
        }
        for (int idx = tid; idx < 512; idx += 128) {
            int row = idx >> 3, v = idx & 7;
            size_t off = ((size_t)e*HDIM + h0 + row) * IDIM + k0 + v*8;
            *(uint4*)(s_bh + row*LDP + v*8) = *(const uint4*)(g_wd_hi + off);
            *(uint4*)(s_bl + row*LDP + v*8) = *(const uint4*)(g_wd_lo + off);
        }
        __syncthreads();
#pragma unroll
        for (int kk = 0; kk < 64; kk += 16) {
            uint32_t ah[2][4], al[2][4];
#pragma unroll
            for (int m = 0; m < 2; m++) {
                int r0 = (rm + m*16 + g_)*LDP + kk + t_*2;
                int r1 = (rm + m*16 + g_ + 8)*LDP + kk + t_*2;
                ah[m][0] = lds32(s_ahi + r0);     ah[m][1] = lds32(s_ahi + r1);
                ah[m][2] = lds32(s_ahi + r0 + 8); ah[m][3] = lds32(s_ahi + r1 + 8);
                al[m][0] = lds32(s_alo + r0);     al[m][1] = lds32(s_alo + r1);
                al[m][2] = lds32(s_alo + r0 + 8); al[m][3] = lds32(s_alo + r1 + 8);
            }
#pragma unroll
            for (int n = 0; n < 8; n++) {
                int b0o = (n*8 + g_)*LDP + kk + t_*2;
                uint32_t bh0 = lds32(s_bh + b0o), bh1 = lds32(s_bh + b0o + 8);
                uint32_t bl0 = lds32(s_bl + b0o), bl1 = lds32(s_bl + b0o + 8);
#pragma unroll
                for (int m = 0; m < 2; m++) {
                    mma16816(cd[m][n], ah[m][0],ah[m][1],ah[m][2],ah[m][3], bh0, bh1);
                    mma16816(cd[m][n], ah[m][0],ah[m][1],ah[m][2],ah[m][3], bl0, bl1);
                    mma16816(cd[m][n], al[m][0],al[m][1],al[m][2],al[m][3], bh0, bh1);
                }
            }
        }
        __syncthreads();
    }

#pragma unroll
    for (int m = 0; m < 2; m++) {
#pragma unroll
        for (int half = 0; half < 2; half++) {
            int lr = rm + m*16 + g_ + half*8;
            int slot = s_slot[lr];
            if (slot < 0) continue;
            float* orow = g_eo + (size_t)slot * HDIM + h0;
#pragma unroll
            for (int n = 0; n < 8; n++) {
                float2 o;
                o.x = cd[m][n][2*half];
                o.y = cd[m][n][2*half+1];
                *(float2*)(orow + n*8 + t_*2) = o;
            }
        }
    }
}

// ======================= 6: combine ==========================================
__global__ void combine_kernel(float* __restrict__ out) {
    int idx = blockIdx.x * 256 + threadIdx.x;
    const int TOTAL = NTOK * HDIM / 4;
    if (idx >= TOTAL) return;
    int t  = idx / (HDIM/4);
    int h4 = idx - t * (HDIM/4);
    float w0 = g_wt[2*t], w1 = g_wt[2*t + 1];
    float4 x0 = *(const float4*)&g_eo[(size_t)(2*t)  *HDIM + h4*4];
    float4 x1 = *(const float4*)&g_eo[(size_t)(2*t+1)*HDIM + h4*4];
    float4 o;
    o.x = w0*x0.x + w1*x1.x;
    o.y = w0*x0.y + w1*x1.y;
    o.z = w0*x0.z + w1*x1.z;
    o.w = w0*x0.w + w1*x1.w;
    ((float4*)out)[idx] = o;
}

// ======================= launch ==============================================
extern "C" void kernel_launch(void* const* d_in, const int* in_sizes, int n_in,
                              void* d_out, int out_size) {
    const float* hs = (const float*)d_in[0];
    const float* wr = (const float*)d_in[1];
    const float* wg = (const float*)d_in[2];
    const float* wu = (const float*)d_in[3];
    const float* wd = (const float*)d_in[4];
    float* out = (float*)d_out;

    cudaFuncSetAttribute(gateup_mma_kernel, cudaFuncAttributeMaxDynamicSharedMemorySize, GU_SMEM_BYTES);
    cudaFuncSetAttribute(down_mma_kernel,   cudaFuncAttributeMaxDynamicSharedMemorySize, DN_SMEM_BYTES);

    init_kernel<<<1, 32>>>();
    split_kernel<<<(NTOK*HDIM/4 + 255)/256, 256>>>(hs, 0, NTOK*HDIM/4);
    split_kernel<<<(NEXP*IDIM*HDIM/4 + 255)/256, 256>>>(wg, 1, NEXP*IDIM*HDIM/4);
    split_kernel<<<(NEXP*IDIM*HDIM/4 + 255)/256, 256>>>(wu, 2, NEXP*IDIM*HDIM/4);
    split_kernel<<<(NEXP*HDIM*IDIM/4 + 255)/256, 256>>>(wd, 3, NEXP*HDIM*IDIM/4);
    router_kernel<<<RBLOCKS, 256>>>(hs, wr);
    aux_kernel<<<1, 256>>>(out, out_size);
    gateup_mma_kernel<<<dim3(IDIM/32, NTOK/128, NEXP), 128, GU_SMEM_BYTES>>>();
    down_mma_kernel<<<dim3(HDIM/64, NTOK/128, NEXP), 128, DN_SMEM_BYTES>>>();
    combine_kernel<<<(NTOK*HDIM/4 + 255)/256, 256>>>(out);
}

// round 5
// speedup vs baseline: 2.8045x; 1.6416x over previous
#include <cuda_runtime.h>
#include <cuda_fp16.h>
#include <cstdint>

#define NTOK  32768          // B*S
#define HDIM  512
#define IDIM  1024
#define NEXP  8
#define NSLOT (2*NTOK)
#define RBLOCKS (NTOK/8)

// ======================= device scratch ======================================
__device__ int   g_cnt[NEXP];
__device__ int   g_list[NEXP*NTOK];
__device__ float g_wt[NSLOT];
__device__ float g_psum[RBLOCKS*NEXP];
__device__ __half g_hs_h[NTOK*HDIM];
__device__ __half g_wg_h[NEXP*IDIM*HDIM];
__device__ __half g_wu_h[NEXP*IDIM*HDIM];
__device__ __half g_wd_h[NEXP*HDIM*IDIM];
__device__ __half g_act_h[67108864];          // NSLOT*IDIM
__device__ float g_eo[(size_t)NSLOT*HDIM];

// ======================= mma.sync helper (fp16 in, fp32 out) =================
__device__ __forceinline__ void mma16816(float* c, uint32_t a0, uint32_t a1,
                                         uint32_t a2, uint32_t a3,
                                         uint32_t b0, uint32_t b1) {
    asm volatile(
        "mma.sync.aligned.m16n8k16.row.col.f32.f16.f16.f32 "
        "{%0,%1,%2,%3}, {%4,%5,%6,%7}, {%8,%9}, {%0,%1,%2,%3};"
        : "+f"(c[0]), "+f"(c[1]), "+f"(c[2]), "+f"(c[3])
        : "r"(a0), "r"(a1), "r"(a2), "r"(a3), "r"(b0), "r"(b1));
}
__device__ __forceinline__ uint32_t lds32(const __half* p) {
    return *(const uint32_t*)p;
}

// ======================= 0: init =============================================
__global__ void init_kernel() {
    if (threadIdx.x < NEXP) g_cnt[threadIdx.x] = 0;
}

// ======================= 1: convert fp32 -> fp16 =============================
// which: 0=hs, 1=wg, 2=wu, 3=wd. Pointers resolved in DEVICE code.
__global__ void __launch_bounds__(256) cvt_kernel(const float* __restrict__ src,
                                                  int which, int n4) {
    int i = blockIdx.x * 256 + threadIdx.x;
    if (i >= n4) return;
    __half* dst;
    switch (which) {
        case 0:  dst = g_hs_h; break;
        case 1:  dst = g_wg_h; break;
        case 2:  dst = g_wu_h; break;
        default: dst = g_wd_h; break;
    }
    float4 v = ((const float4*)src)[i];
    __half2 p0 = __floats2half2_rn(v.x, v.y);
    __half2 p1 = __floats2half2_rn(v.z, v.w);
    ((uint2*)dst)[i] = make_uint2(*(uint32_t*)&p0, *(uint32_t*)&p1);
}

// ======================= 2: router ===========================================
__global__ void __launch_bounds__(256) router_kernel(const float* __restrict__ hs,
                                                     const float* __restrict__ wr) {
    __shared__ float swr[NEXP*HDIM];
    __shared__ float sprob[8][NEXP];
    int tid = threadIdx.x;
    for (int i = tid; i < NEXP*HDIM; i += 256) swr[i] = wr[i];
    __syncthreads();

    int warp = tid >> 5, lane = tid & 31;
    int t = blockIdx.x * 8 + warp;
    const float* hrow = hs + (size_t)t * HDIM;

    float acc[NEXP];
#pragma unroll
    for (int e = 0; e < NEXP; e++) acc[e] = 0.f;
    for (int j = lane; j < HDIM; j += 32) {
        float hv = hrow[j];
#pragma unroll
        for (int e = 0; e < NEXP; e++) acc[e] = fmaf(hv, swr[e*HDIM + j], acc[e]);
    }
#pragma unroll
    for (int e = 0; e < NEXP; e++) {
#pragma unroll
        for (int o = 16; o > 0; o >>= 1) acc[e] += __shfl_xor_sync(0xffffffffu, acc[e], o);
    }

    if (lane == 0) {
        int e0 = 0; float v0 = acc[0];
#pragma unroll
        for (int e = 1; e < NEXP; e++) if (acc[e] > v0) { v0 = acc[e]; e0 = e; }
        int e1 = -1; float v1 = -1e30f;
#pragma unroll
        for (int e = 0; e < NEXP; e++) if (e != e0 && acc[e] > v1) { v1 = acc[e]; e1 = e; }

        float z  = __expf(v1 - v0);
        float p1 = z / (1.f + z);
        g_wt[2*t]     = 1.f - p1;
        g_wt[2*t + 1] = p1;

        int pos0 = atomicAdd(&g_cnt[e0], 1);
        g_list[e0*NTOK + pos0] = 2*t;
        int pos1 = atomicAdd(&g_cnt[e1], 1);
        g_list[e1*NTOK + pos1] = 2*t + 1;

        float s = 0.f, pe[NEXP];
#pragma unroll
        for (int e = 0; e < NEXP; e++) { pe[e] = __expf(acc[e] - v0); s += pe[e]; }
        float inv = 1.f / s;
#pragma unroll
        for (int e = 0; e < NEXP; e++) sprob[warp][e] = pe[e] * inv;
    }
    __syncthreads();
    if (tid < NEXP) {
        float s = 0.f;
#pragma unroll
        for (int w = 0; w < 8; w++) s += sprob[w][tid];
        g_psum[blockIdx.x*NEXP + tid] = s;
    }
}

// ======================= 3: aux loss =========================================
__global__ void aux_kernel(float* __restrict__ out, int out_size) {
    __shared__ float part[256];
    int tid = threadIdx.x;
    int e = tid & 7, c = tid >> 3;
    const int CH = RBLOCKS / 32;
    float s = 0.f;
    for (int b = c*CH; b < (c+1)*CH; b++) s += g_psum[b*NEXP + e];
    part[tid] = s;
    __syncthreads();
    if (tid < NEXP) {
        float tot = 0.f;
        for (int cc = 0; cc < 32; cc++) tot += part[cc*8 + tid];
        part[tid] = (tot / (float)NTOK) * ((float)g_cnt[tid] / (float)NSLOT) * (float)NEXP;
    }
    __syncthreads();
    if (tid == 0 && out_size > NTOK*HDIM) {
        float a = 0.f;
#pragma unroll
        for (int ee = 0; ee < NEXP; ee++) a += part[ee];
        out[(size_t)NTOK*HDIM] = a;
    }
}

// ======================= 4: gate/up mma.sync GEMM (fp16 single) ==============
// CTA: 128 tokens x 32 I, 4 warps (each 32 rows x 32 cols, g AND u).
// K=512 in 64-chunks, padded smem stride 72.
#define LDP 72
#define GU_A   (128*LDP)
#define GU_B   (32*LDP)
#define GU_SMEM_BYTES ((GU_A + 2*GU_B)*2 + 1024)
__global__ void __launch_bounds__(128) gateup_mma_kernel() {
    int e   = blockIdx.z;
    int cnt = g_cnt[e];
    int p0  = blockIdx.y * 128;
    if (p0 >= cnt) return;
    int i0  = blockIdx.x * 32;

    extern __shared__ char smem_raw[];
    __half* s_a  = (__half*)smem_raw;
    __half* s_bg = s_a + GU_A;
    __half* s_bu = s_bg + GU_B;
    int* s_rowoff = (int*)(s_bu + GU_B);
    int* s_slot   = s_rowoff + 128;

    int tid = threadIdx.x, wid = tid >> 5, lane = tid & 31;
    int g_ = lane >> 2, t_ = lane & 3;

    {
        int p = p0 + tid;
        int cl = (p < cnt) ? p : (cnt - 1);
        int sl = g_list[e*NTOK + cl];
        s_rowoff[tid] = (sl >> 1) * HDIM;
        s_slot[tid]   = (p < cnt) ? sl : -1;
    }
    __syncthreads();

    float cg[2][4][4], cu[2][4][4];
#pragma unroll
    for (int m = 0; m < 2; m++)
#pragma unroll
        for (int n = 0; n < 4; n++)
#pragma unroll
            for (int q = 0; q < 4; q++) { cg[m][n][q] = 0.f; cu[m][n][q] = 0.f; }

    int rm = wid * 32;
    for (int c = 0; c < 8; c++) {
        int k0 = c * 64;
        // load A (128 rows x 64 k)
        for (int idx = tid; idx < 1024; idx += 128) {
            int row = idx >> 3, v = idx & 7;
            int off = s_rowoff[row] + k0 + v*8;
            *(uint4*)(s_a + row*LDP + v*8) = *(const uint4*)(g_hs_h + off);
        }
        // load B (32 rows x 64 k) for gate and up
        for (int idx = tid; idx < 256; idx += 128) {
            int row = idx >> 3, v = idx & 7;
            size_t off = ((size_t)e*IDIM + i0 + row) * HDIM + k0 + v*8;
            *(uint4*)(s_bg + row*LDP + v*8) = *(const uint4*)(g_wg_h + off);
            *(uint4*)(s_bu + row*LDP + v*8) = *(const uint4*)(g_wu_h + off);
        }
        __syncthreads();
#pragma unroll
        for (int kk = 0; kk < 64; kk += 16) {
            uint32_t ar[2][4];
#pragma unroll
            for (int m = 0; m < 2; m++) {
                int r0 = (rm + m*16 + g_)*LDP + kk + t_*2;
                int r1 = (rm + m*16 + g_ + 8)*LDP + kk + t_*2;
                ar[m][0] = lds32(s_a + r0);     ar[m][1] = lds32(s_a + r1);
                ar[m][2] = lds32(s_a + r0 + 8); ar[m][3] = lds32(s_a + r1 + 8);
            }
#pragma unroll
            for (int n = 0; n < 4; n++) {
                int b0o = (n*8 + g_)*LDP + kk + t_*2;
                uint32_t gb0 = lds32(s_bg + b0o), gb1 = lds32(s_bg + b0o + 8);
                uint32_t ub0 = lds32(s_bu + b0o), ub1 = lds32(s_bu + b0o + 8);
#pragma unroll
                for (int m = 0; m < 2; m++) {
                    mma16816(cg[m][n], ar[m][0],ar[m][1],ar[m][2],ar[m][3], gb0, gb1);
                    mma16816(cu[m][n], ar[m][0],ar[m][1],ar[m][2],ar[m][3], ub0, ub1);
                }
            }
        }
        __syncthreads();
    }

    // epilogue: act = silu(g)*u -> fp16 by slot
#pragma unroll
    for (int m = 0; m < 2; m++) {
#pragma unroll
        for (int half_ = 0; half_ < 2; half_++) {
            int lr = rm + m*16 + g_ + half_*8;
            int slot = s_slot[lr];
            if (slot < 0) continue;
            __half* oh = g_act_h + (size_t)slot * IDIM + i0;
#pragma unroll
            for (int n = 0; n < 4; n++) {
                float gv0 = cg[m][n][2*half_],   uv0 = cu[m][n][2*half_];
                float gv1 = cg[m][n][2*half_+1], uv1 = cu[m][n][2*half_+1];
                float a0 = (gv0 / (1.f + __expf(-gv0))) * uv0;
                float a1 = (gv1 / (1.f + __expf(-gv1))) * uv1;
                __half2 hp = __floats2half2_rn(a0, a1);
                *(uint32_t*)(oh + n*8 + t_*2) = *(uint32_t*)&hp;
            }
        }
    }
}

// ======================= 5: down mma.sync GEMM (fp16 single) =================
// CTA: 128 slots x 64 h, 4 warps (each 32 rows x 64 cols). K=1024 in 64-chunks.
#define DN_A   (128*LDP)
#define DN_B   (64*LDP)
#define DN_SMEM_BYTES ((DN_A + DN_B)*2 + 1024)
__global__ void __launch_bounds__(128) down_mma_kernel() {
    int e   = blockIdx.z;
    int cnt = g_cnt[e];
    int p0  = blockIdx.y * 128;
    if (p0 >= cnt) return;
    int h0  = blockIdx.x * 64;

    extern __shared__ char smem_raw[];
    __half* s_a = (__half*)smem_raw;
    __half* s_b = s_a + DN_A;
    int* s_rowoff = (int*)(s_b + DN_B);
    int* s_slot   = s_rowoff + 128;

    int tid = threadIdx.x, wid = tid >> 5, lane = tid & 31;
    int g_ = lane >> 2, t_ = lane & 3;

    {
        int p = p0 + tid;
        int cl = (p < cnt) ? p : (cnt - 1);
        int sl = g_list[e*NTOK + cl];
        s_rowoff[tid] = sl * IDIM;
        s_slot[tid]   = (p < cnt) ? sl : -1;
    }
    __syncthreads();

    float cd[2][8][4];
#pragma unroll
    for (int m = 0; m < 2; m++)
#pragma unroll
        for (int n = 0; n < 8; n++)
#pragma unroll
            for (int q = 0; q < 4; q++) cd[m][n][q] = 0.f;

    int rm = wid * 32;
    for (int c = 0; c < 16; c++) {
        int k0 = c * 64;
        for (int idx = tid; idx < 1024; idx += 128) {
            int row = idx >> 3, v = idx & 7;
            int off = s_rowoff[row] + k0 + v*8;
            *(uint4*)(s_a + row*LDP + v*8) = *(const uint4*)(g_act_h + off);
        }
        for (int idx = tid; idx < 512; idx += 128) {
            int row = idx >> 3, v = idx & 7;
            size_t off = ((size_t)e*HDIM + h0 + row) * IDIM + k0 + v*8;
            *(uint4*)(s_b + row*LDP + v*8) = *(const uint4*)(g_wd_h + off);
        }
        __syncthreads();
#pragma unroll
        for (int kk = 0; kk < 64; kk += 16) {
            uint32_t ar[2][4];
#pragma unroll
            for (int m = 0; m < 2; m++) {
                int r0 = (rm + m*16 + g_)*LDP + kk + t_*2;
                int r1 = (rm + m*16 + g_ + 8)*LDP + kk + t_*2;
                ar[m][0] = lds32(s_a + r0);     ar[m][1] = lds32(s_a + r1);
                ar[m][2] = lds32(s_a + r0 + 8); ar[m][3] = lds32(s_a + r1 + 8);
            }
#pragma unroll
            for (int n = 0; n < 8; n++) {
                int b0o = (n*8 + g_)*LDP + kk + t_*2;
                uint32_t b0 = lds32(s_b + b0o), b1 = lds32(s_b + b0o + 8);
#pragma unroll
                for (int m = 0; m < 2; m++) {
                    mma16816(cd[m][n], ar[m][0],ar[m][1],ar[m][2],ar[m][3], b0, b1);
                }
            }
        }
        __syncthreads();
    }

#pragma unroll
    for (int m = 0; m < 2; m++) {
#pragma unroll
        for (int half_ = 0; half_ < 2; half_++) {
            int lr = rm + m*16 + g_ + half_*8;
            int slot = s_slot[lr];
            if (slot < 0) continue;
            float* orow = g_eo + (size_t)slot * HDIM + h0;
#pragma unroll
            for (int n = 0; n < 8; n++) {
                float2 o;
                o.x = cd[m][n][2*half_];
                o.y = cd[m][n][2*half_+1];
                *(float2*)(orow + n*8 + t_*2) = o;
            }
        }
    }
}

// ======================= 6: combine ==========================================
__global__ void combine_kernel(float* __restrict__ out) {
    int idx = blockIdx.x * 256 + threadIdx.x;
    const int TOTAL = NTOK * HDIM / 4;
    if (idx >= TOTAL) return;
    int t  = idx / (HDIM/4);
    int h4 = idx - t * (HDIM/4);
    float w0 = g_wt[2*t], w1 = g_wt[2*t + 1];
    float4 x0 = *(const float4*)&g_eo[(size_t)(2*t)  *HDIM + h4*4];
    float4 x1 = *(const float4*)&g_eo[(size_t)(2*t+1)*HDIM + h4*4];
    float4 o;
    o.x = w0*x0.x + w1*x1.x;
    o.y = w0*x0.y + w1*x1.y;
    o.z = w0*x0.z + w1*x1.z;
    o.w = w0*x0.w + w1*x1.w;
    ((float4*)out)[idx] = o;
}

// ======================= launch ==============================================
extern "C" void kernel_launch(void* const* d_in, const int* in_sizes, int n_in,
                              void* d_out, int out_size) {
    const float* hs = (const float*)d_in[0];
    const float* wr = (const float*)d_in[1];
    const float* wg = (const float*)d_in[2];
    const float* wu = (const float*)d_in[3];
    const float* wd = (const float*)d_in[4];
    float* out = (float*)d_out;

    cudaFuncSetAttribute(gateup_mma_kernel, cudaFuncAttributeMaxDynamicSharedMemorySize, GU_SMEM_BYTES);
    cudaFuncSetAttribute(down_mma_kernel,   cudaFuncAttributeMaxDynamicSharedMemorySize, DN_SMEM_BYTES);

    init_kernel<<<1, 32>>>();
    cvt_kernel<<<(NTOK*HDIM/4 + 255)/256, 256>>>(hs, 0, NTOK*HDIM/4);
    cvt_kernel<<<(NEXP*IDIM*HDIM/4 + 255)/256, 256>>>(wg, 1, NEXP*IDIM*HDIM/4);
    cvt_kernel<<<(NEXP*IDIM*HDIM/4 + 255)/256, 256>>>(wu, 2, NEXP*IDIM*HDIM/4);
    cvt_kernel<<<(NEXP*HDIM*IDIM/4 + 255)/256, 256>>>(wd, 3, NEXP*HDIM*IDIM/4);
    router_kernel<<<RBLOCKS, 256>>>(hs, wr);
    aux_kernel<<<1, 256>>>(out, out_size);
    gateup_mma_kernel<<<dim3(IDIM/32, NTOK/128, NEXP), 128, GU_SMEM_BYTES>>>();
    down_mma_kernel<<<dim3(HDIM/64, NTOK/128, NEXP), 128, DN_SMEM_BYTES>>>();
    combine_kernel<<<(NTOK*HDIM/4 + 255)/256, 256>>>(out);
}

// round 6
// speedup vs baseline: 6.0405x; 2.1539x over previous
#include <cuda_runtime.h>
#include <cuda_fp16.h>
#include <cstdint>

#define NTOK  32768          // B*S
#define HDIM  512
#define IDIM  1024
#define NEXP  8
#define NSLOT (2*NTOK)
#define RBLOCKS (NTOK/8)
#define LDP   72             // padded smem stride (halves)

// ======================= device scratch ======================================
__device__ int   g_cnt[NEXP];
__device__ int   g_list[NEXP*NTOK];
__device__ float g_wt[NSLOT];
__device__ float g_psum[RBLOCKS*NEXP];
__device__ __half g_hs_h[NTOK*HDIM];
__device__ __half g_wg_h[NEXP*IDIM*HDIM];
__device__ __half g_wu_h[NEXP*IDIM*HDIM];
__device__ __half g_wd_h[NEXP*HDIM*IDIM];
__device__ __half g_act_h[67108864];          // NSLOT*IDIM

// ======================= PTX helpers =========================================
__device__ __forceinline__ uint32_t smem_u32(const void* p) {
    uint32_t a;
    asm("{ .reg .u64 t; cvta.to.shared.u64 t, %1; cvt.u32.u64 %0, t; }" : "=r"(a) : "l"(p));
    return a;
}
__device__ __forceinline__ void cpasync16(uint32_t dst, const void* src) {
    asm volatile("cp.async.cg.shared.global [%0], [%1], 16;" :: "r"(dst), "l"(src));
}
#define CP_COMMIT() asm volatile("cp.async.commit_group;" ::: "memory")
#define CP_WAIT1()  asm volatile("cp.async.wait_group 1;" ::: "memory")
#define CP_WAIT0()  asm volatile("cp.async.wait_group 0;" ::: "memory")
__device__ __forceinline__ void ldsm4(uint32_t* r, uint32_t addr) {
    asm volatile("ldmatrix.sync.aligned.m8n8.x4.shared.b16 {%0,%1,%2,%3}, [%4];"
        : "=r"(r[0]), "=r"(r[1]), "=r"(r[2]), "=r"(r[3]) : "r"(addr));
}
__device__ __forceinline__ void mma16816(float* c, uint32_t a0, uint32_t a1,
                                         uint32_t a2, uint32_t a3,
                                         uint32_t b0, uint32_t b1) {
    asm volatile(
        "mma.sync.aligned.m16n8k16.row.col.f32.f16.f16.f32 "
        "{%0,%1,%2,%3}, {%4,%5,%6,%7}, {%8,%9}, {%0,%1,%2,%3};"
        : "+f"(c[0]), "+f"(c[1]), "+f"(c[2]), "+f"(c[3])
        : "r"(a0), "r"(a1), "r"(a2), "r"(a3), "r"(b0), "r"(b1));
}

// ======================= 0: init + zero output ===============================
__global__ void init_kernel() {
    if (threadIdx.x < NEXP) g_cnt[threadIdx.x] = 0;
}
__global__ void __launch_bounds__(256) zero_out_kernel(float* __restrict__ out) {
    int i = blockIdx.x * 256 + threadIdx.x;
    if (i < NTOK*HDIM/4) ((float4*)out)[i] = make_float4(0.f, 0.f, 0.f, 0.f);
}

// ======================= 1: convert fp32 -> fp16 =============================
__global__ void __launch_bounds__(256) cvt_kernel(const float* __restrict__ src,
                                                  int which, int n4) {
    int i = blockIdx.x * 256 + threadIdx.x;
    if (i >= n4) return;
    __half* dst;
    switch (which) {
        case 0:  dst = g_hs_h; break;
        case 1:  dst = g_wg_h; break;
        case 2:  dst = g_wu_h; break;
        default: dst = g_wd_h; break;
    }
    float4 v = ((const float4*)src)[i];
    __half2 p0 = __floats2half2_rn(v.x, v.y);
    __half2 p1 = __floats2half2_rn(v.z, v.w);
    ((uint2*)dst)[i] = make_uint2(*(uint32_t*)&p0, *(uint32_t*)&p1);
}

// ======================= 2: router ===========================================
__global__ void __launch_bounds__(256) router_kernel(const float* __restrict__ hs,
                                                     const float* __restrict__ wr) {
    __shared__ float swr[NEXP*HDIM];
    __shared__ float sprob[8][NEXP];
    int tid = threadIdx.x;
    for (int i = tid; i < NEXP*HDIM; i += 256) swr[i] = wr[i];
    __syncthreads();

    int warp = tid >> 5, lane = tid & 31;
    int t = blockIdx.x * 8 + warp;
    const float* hrow = hs + (size_t)t * HDIM;

    float acc[NEXP];
#pragma unroll
    for (int e = 0; e < NEXP; e++) acc[e] = 0.f;
    for (int j = lane; j < HDIM; j += 32) {
        float hv = hrow[j];
#pragma unroll
        for (int e = 0; e < NEXP; e++) acc[e] = fmaf(hv, swr[e*HDIM + j], acc[e]);
    }
#pragma unroll
    for (int e = 0; e < NEXP; e++) {
#pragma unroll
        for (int o = 16; o > 0; o >>= 1) acc[e] += __shfl_xor_sync(0xffffffffu, acc[e], o);
    }

    if (lane == 0) {
        int e0 = 0; float v0 = acc[0];
#pragma unroll
        for (int e = 1; e < NEXP; e++) if (acc[e] > v0) { v0 = acc[e]; e0 = e; }
        int e1 = -1; float v1 = -1e30f;
#pragma unroll
        for (int e = 0; e < NEXP; e++) if (e != e0 && acc[e] > v1) { v1 = acc[e]; e1 = e; }

        float z  = __expf(v1 - v0);
        float p1 = z / (1.f + z);
        g_wt[2*t]     = 1.f - p1;
        g_wt[2*t + 1] = p1;

        int pos0 = atomicAdd(&g_cnt[e0], 1);
        g_list[e0*NTOK + pos0] = 2*t;
        int pos1 = atomicAdd(&g_cnt[e1], 1);
        g_list[e1*NTOK + pos1] = 2*t + 1;

        float s = 0.f, pe[NEXP];
#pragma unroll
        for (int e = 0; e < NEXP; e++) { pe[e] = __expf(acc[e] - v0); s += pe[e]; }
        float inv = 1.f / s;
#pragma unroll
        for (int e = 0; e < NEXP; e++) sprob[warp][e] = pe[e] * inv;
    }
    __syncthreads();
    if (tid < NEXP) {
        float s = 0.f;
#pragma unroll
        for (int w = 0; w < 8; w++) s += sprob[w][tid];
        g_psum[blockIdx.x*NEXP + tid] = s;
    }
}

// ======================= 3: aux loss =========================================
__global__ void aux_kernel(float* __restrict__ out, int out_size) {
    __shared__ float part[256];
    int tid = threadIdx.x;
    int e = tid & 7, c = tid >> 3;
    const int CH = RBLOCKS / 32;
    float s = 0.f;
    for (int b = c*CH; b < (c+1)*CH; b++) s += g_psum[b*NEXP + e];
    part[tid] = s;
    __syncthreads();
    if (tid < NEXP) {
        float tot = 0.f;
        for (int cc = 0; cc < 32; cc++) tot += part[cc*8 + tid];
        part[tid] = (tot / (float)NTOK) * ((float)g_cnt[tid] / (float)NSLOT) * (float)NEXP;
    }
    __syncthreads();
    if (tid == 0 && out_size > NTOK*HDIM) {
        float a = 0.f;
#pragma unroll
        for (int ee = 0; ee < NEXP; ee++) a += part[ee];
        out[(size_t)NTOK*HDIM] = a;
    }
}

// ======================= 4: gate/up GEMM (cp.async + ldmatrix) ===============
// CTA 256 thr: tile 128 tokens x 64 I. Warp grid 4(row) x 2(col): 32x32 each.
// K=512, 64-chunks, 2-stage cp.async double buffer.
#define GU_AE  (128*LDP)
#define GU_BE  (64*LDP)
#define GU_BUF (GU_AE + 2*GU_BE)
#define GU_SMEM_BYTES (2*GU_BUF*2 + 1024)
__global__ void __launch_bounds__(256) gateup_mma_kernel() {
    int e   = blockIdx.z;
    int cnt = g_cnt[e];
    int p0  = blockIdx.y * 128;
    if (p0 >= cnt) return;
    int i0  = blockIdx.x * 64;

    extern __shared__ __half smem[];
    int* s_rowoff = (int*)(smem + 2*GU_BUF);
    int* s_slot   = s_rowoff + 128;

    int tid = threadIdx.x, wid = tid >> 5, lane = tid & 31;
    int wr = wid & 3, wc = wid >> 2;

    if (tid < 128) {
        int p = p0 + tid;
        int cl = (p < cnt) ? p : (cnt - 1);
        int sl = g_list[e*NTOK + cl];
        s_rowoff[tid] = (sl >> 1) * HDIM;
        s_slot[tid]   = (p < cnt) ? sl : -1;
    }
    __syncthreads();
    uint32_t sbase = smem_u32(smem);

    auto load_chunk = [&](int c, int st) {
        int k0 = c * 64;
        uint32_t a_s  = sbase + st*GU_BUF*2;
        uint32_t bg_s = a_s + GU_AE*2;
        uint32_t bu_s = bg_s + GU_BE*2;
#pragma unroll
        for (int it = 0; it < 4; it++) {
            int idx = tid + it*256;
            int row = idx >> 3, v = idx & 7;
            cpasync16(a_s + (row*LDP + v*8)*2, g_hs_h + s_rowoff[row] + k0 + v*8);
        }
#pragma unroll
        for (int it = 0; it < 2; it++) {
            int idx = tid + it*256;
            int row = idx >> 3, v = idx & 7;
            size_t off = ((size_t)e*IDIM + i0 + row) * HDIM + k0 + v*8;
            cpasync16(bg_s + (row*LDP + v*8)*2, g_wg_h + off);
            cpasync16(bu_s + (row*LDP + v*8)*2, g_wu_h + off);
        }
        CP_COMMIT();
    };

    float cg[2][4][4], cu[2][4][4];
#pragma unroll
    for (int m = 0; m < 2; m++)
#pragma unroll
        for (int n = 0; n < 4; n++)
#pragma unroll
            for (int q = 0; q < 4; q++) { cg[m][n][q] = 0.f; cu[m][n][q] = 0.f; }

    int lrow = lane & 7, seg = lane >> 3;
    int rowadd = (seg & 1) ? 8 : 0, coladd = (seg >= 2) ? 8 : 0;   // A form
    int browadd = (seg >= 2) ? 8 : 0, bcoladd = (seg & 1) ? 8 : 0; // B form

    load_chunk(0, 0);
    for (int c = 0; c < 8; c++) {
        int st = c & 1;
        if (c < 7) { load_chunk(c + 1, st ^ 1); CP_WAIT1(); } else CP_WAIT0();
        __syncthreads();
        uint32_t a_s  = sbase + st*GU_BUF*2;
        uint32_t bg_s = a_s + GU_AE*2;
        uint32_t bu_s = bg_s + GU_BE*2;
#pragma unroll
        for (int kk = 0; kk < 64; kk += 16) {
            uint32_t a[2][4], bg[2][4], bu[2][4];
#pragma unroll
            for (int m = 0; m < 2; m++) {
                int row = wr*32 + m*16 + lrow + rowadd;
                ldsm4(a[m], a_s + (row*LDP + kk + coladd)*2);
            }
#pragma unroll
            for (int j = 0; j < 2; j++) {
                int row = wc*32 + j*16 + lrow + browadd;
                ldsm4(bg[j], bg_s + (row*LDP + kk + bcoladd)*2);
                ldsm4(bu[j], bu_s + (row*LDP + kk + bcoladd)*2);
            }
#pragma unroll
            for (int n = 0; n < 4; n++) {
                int j = n >> 1, s2 = (n & 1) * 2;
#pragma unroll
                for (int m = 0; m < 2; m++) {
                    mma16816(cg[m][n], a[m][0],a[m][1],a[m][2],a[m][3], bg[j][s2], bg[j][s2+1]);
                    mma16816(cu[m][n], a[m][0],a[m][1],a[m][2],a[m][3], bu[j][s2], bu[j][s2+1]);
                }
            }
        }
        __syncthreads();
    }

    // epilogue: act = silu(g)*u -> fp16 by slot
    int g_ = lane >> 2, t_ = lane & 3;
#pragma unroll
    for (int m = 0; m < 2; m++) {
#pragma unroll
        for (int half_ = 0; half_ < 2; half_++) {
            int lr = wr*32 + m*16 + g_ + half_*8;
            int slot = s_slot[lr];
            if (slot < 0) continue;
            __half* oh = g_act_h + (size_t)slot * IDIM + i0 + wc*32;
#pragma unroll
            for (int n = 0; n < 4; n++) {
                float gv0 = cg[m][n][2*half_],   uv0 = cu[m][n][2*half_];
                float gv1 = cg[m][n][2*half_+1], uv1 = cu[m][n][2*half_+1];
                float a0 = (gv0 / (1.f + __expf(-gv0))) * uv0;
                float a1 = (gv1 / (1.f + __expf(-gv1))) * uv1;
                __half2 hp = __floats2half2_rn(a0, a1);
                *(uint32_t*)(oh + n*8 + t_*2) = *(uint32_t*)&hp;
            }
        }
    }
}

// ======================= 5: down GEMM + fused combine ========================
// CTA 256 thr: tile 128 slots x 128 h. Warp grid 4x2: 32x64 each. K=1024.
// Epilogue: atomicAdd of w_slot * val directly into out (2 adds/elem, fp32
// add commutative -> deterministic).
#define DN_AE  (128*LDP)
#define DN_BE  (128*LDP)
#define DN_BUF (DN_AE + DN_BE)
#define DN_SMEM_BYTES (2*DN_BUF*2 + 2048)
__global__ void __launch_bounds__(256) down_mma_kernel(float* __restrict__ out) {
    int e   = blockIdx.z;
    int cnt = g_cnt[e];
    int p0  = blockIdx.y * 128;
    if (p0 >= cnt) return;
    int h0  = blockIdx.x * 128;

    extern __shared__ __half smem[];
    int*   s_rowoff = (int*)(smem + 2*DN_BUF);
    int*   s_slot   = s_rowoff + 128;
    float* s_w      = (float*)(s_slot + 128);

    int tid = threadIdx.x, wid = tid >> 5, lane = tid & 31;
    int wr = wid & 3, wc = wid >> 2;

    if (tid < 128) {
        int p = p0 + tid;
        int cl = (p < cnt) ? p : (cnt - 1);
        int sl = g_list[e*NTOK + cl];
        s_rowoff[tid] = sl * IDIM;
        s_slot[tid]   = (p < cnt) ? sl : -1;
        s_w[tid]      = g_wt[sl];
    }
    __syncthreads();
    uint32_t sbase = smem_u32(smem);

    auto load_chunk = [&](int c, int st) {
        int k0 = c * 64;
        uint32_t a_s = sbase + st*DN_BUF*2;
        uint32_t b_s = a_s + DN_AE*2;
#pragma unroll
        for (int it = 0; it < 4; it++) {
            int idx = tid + it*256;
            int row = idx >> 3, v = idx & 7;
            cpasync16(a_s + (row*LDP + v*8)*2, g_act_h + s_rowoff[row] + k0 + v*8);
        }
#pragma unroll
        for (int it = 0; it < 4; it++) {
            int idx = tid + it*256;
            int row = idx >> 3, v = idx & 7;
            size_t off = ((size_t)e*HDIM + h0 + row) * IDIM + k0 + v*8;
            cpasync16(b_s + (row*LDP + v*8)*2, g_wd_h + off);
        }
        CP_COMMIT();
    };

    float cd[2][8][4];
#pragma unroll
    for (int m = 0; m < 2; m++)
#pragma unroll
        for (int n = 0; n < 8; n++)
#pragma unroll
            for (int q = 0; q < 4; q++) cd[m][n][q] = 0.f;

    int lrow = lane & 7, seg = lane >> 3;
    int rowadd = (seg & 1) ? 8 : 0, coladd = (seg >= 2) ? 8 : 0;
    int browadd = (seg >= 2) ? 8 : 0, bcoladd = (seg & 1) ? 8 : 0;

    load_chunk(0, 0);
    for (int c = 0; c < 16; c++) {
        int st = c & 1;
        if (c < 15) { load_chunk(c + 1, st ^ 1); CP_WAIT1(); } else CP_WAIT0();
        __syncthreads();
        uint32_t a_s = sbase + st*DN_BUF*2;
        uint32_t b_s = a_s + DN_AE*2;
#pragma unroll
        for (int kk = 0; kk < 64; kk += 16) {
            uint32_t a[2][4], bb[4][4];
#pragma unroll
            for (int m = 0; m < 2; m++) {
                int row = wr*32 + m*16 + lrow + rowadd;
                ldsm4(a[m], a_s + (row*LDP + kk + coladd)*2);
            }
#pragma unroll
            for (int j = 0; j < 4; j++) {
                int row = wc*64 + j*16 + lrow + browadd;
                ldsm4(bb[j], b_s + (row*LDP + kk + bcoladd)*2);
            }
#pragma unroll
            for (int n = 0; n < 8; n++) {
                int j = n >> 1, s2 = (n & 1) * 2;
#pragma unroll
                for (int m = 0; m < 2; m++) {
                    mma16816(cd[m][n], a[m][0],a[m][1],a[m][2],a[m][3], bb[j][s2], bb[j][s2+1]);
                }
            }
        }
        __syncthreads();
    }

    // epilogue: out[token] += w * val (atomic, 2 contributions per element)
    int g_ = lane >> 2, t_ = lane & 3;
#pragma unroll
    for (int m = 0; m < 2; m++) {
#pragma unroll
        for (int half_ = 0; half_ < 2; half_++) {
            int lr = wr*32 + m*16 + g_ + half_*8;
            int slot = s_slot[lr];
            if (slot < 0) continue;
            float w = s_w[lr];
            float* orow = out + (size_t)(slot >> 1) * HDIM + h0 + wc*64;
#pragma unroll
            for (int n = 0; n < 8; n++) {
                atomicAdd(orow + n*8 + t_*2,     w * cd[m][n][2*half_]);
                atomicAdd(orow + n*8 + t_*2 + 1, w * cd[m][n][2*half_+1]);
            }
        }
    }
}

// ======================= launch ==============================================
extern "C" void kernel_launch(void* const* d_in, const int* in_sizes, int n_in,
                              void* d_out, int out_size) {
    const float* hs = (const float*)d_in[0];
    const float* wr = (const float*)d_in[1];
    const float* wg = (const float*)d_in[2];
    const float* wu = (const float*)d_in[3];
    const float* wd = (const float*)d_in[4];
    float* out = (float*)d_out;

    cudaFuncSetAttribute(gateup_mma_kernel, cudaFuncAttributeMaxDynamicSharedMemorySize, GU_SMEM_BYTES);
    cudaFuncSetAttribute(down_mma_kernel,   cudaFuncAttributeMaxDynamicSharedMemorySize, DN_SMEM_BYTES);

    init_kernel<<<1, 32>>>();
    zero_out_kernel<<<(NTOK*HDIM/4 + 255)/256, 256>>>(out);
    cvt_kernel<<<(NTOK*HDIM/4 + 255)/256, 256>>>(hs, 0, NTOK*HDIM/4);
    cvt_kernel<<<(NEXP*IDIM*HDIM/4 + 255)/256, 256>>>(wg, 1, NEXP*IDIM*HDIM/4);
    cvt_kernel<<<(NEXP*IDIM*HDIM/4 + 255)/256, 256>>>(wu, 2, NEXP*IDIM*HDIM/4);
    cvt_kernel<<<(NEXP*HDIM*IDIM/4 + 255)/256, 256>>>(wd, 3, NEXP*HDIM*IDIM/4);
    router_kernel<<<RBLOCKS, 256>>>(hs, wr);
    aux_kernel<<<1, 256>>>(out, out_size);
    gateup_mma_kernel<<<dim3(IDIM/64, NTOK/128, NEXP), 256, GU_SMEM_BYTES>>>();
    down_mma_kernel<<<dim3(HDIM/128, NTOK/128, NEXP), 256, DN_SMEM_BYTES>>>(out);
}

// round 7
// speedup vs baseline: 6.1942x; 1.0254x over previous
#include <cuda_runtime.h>
#include <cuda_fp16.h>
#include <cstdint>

#define NTOK  32768          // B*S
#define HDIM  512
#define IDIM  1024
#define NEXP  8
#define NSLOT (2*NTOK)
#define RBLOCKS (NTOK/8)
#define LDP   72             // padded smem stride (halves)

// ======================= device scratch ======================================
__device__ int   g_cnt[NEXP];
__device__ int   g_list[NEXP*NTOK];
__device__ float g_wt[NSLOT];
__device__ float g_psum[RBLOCKS*NEXP];
__device__ __half g_hs_h[NTOK*HDIM];
__device__ __half g_wg_h[NEXP*IDIM*HDIM];
__device__ __half g_wu_h[NEXP*IDIM*HDIM];
__device__ __half g_wd_h[NEXP*HDIM*IDIM];
__device__ __half g_act_h[67108864];          // NSLOT*IDIM

// ======================= PTX helpers =========================================
__device__ __forceinline__ uint32_t smem_u32(const void* p) {
    uint32_t a;
    asm("{ .reg .u64 t; cvta.to.shared.u64 t, %1; cvt.u32.u64 %0, t; }" : "=r"(a) : "l"(p));
    return a;
}
__device__ __forceinline__ void cpasync16(uint32_t dst, const void* src) {
    asm volatile("cp.async.cg.shared.global [%0], [%1], 16;" :: "r"(dst), "l"(src));
}
#define CP_COMMIT() asm volatile("cp.async.commit_group;" ::: "memory")
#define CP_WAIT1()  asm volatile("cp.async.wait_group 1;" ::: "memory")
#define CP_WAIT0()  asm volatile("cp.async.wait_group 0;" ::: "memory")
__device__ __forceinline__ void ldsm4(uint32_t* r, uint32_t addr) {
    asm volatile("ldmatrix.sync.aligned.m8n8.x4.shared.b16 {%0,%1,%2,%3}, [%4];"
        : "=r"(r[0]), "=r"(r[1]), "=r"(r[2]), "=r"(r[3]) : "r"(addr));
}
__device__ __forceinline__ void mma16816(float* c, uint32_t a0, uint32_t a1,
                                         uint32_t a2, uint32_t a3,
                                         uint32_t b0, uint32_t b1) {
    asm volatile(
        "mma.sync.aligned.m16n8k16.row.col.f32.f16.f16.f32 "
        "{%0,%1,%2,%3}, {%4,%5,%6,%7}, {%8,%9}, {%0,%1,%2,%3};"
        : "+f"(c[0]), "+f"(c[1]), "+f"(c[2]), "+f"(c[3])
        : "r"(a0), "r"(a1), "r"(a2), "r"(a3), "r"(b0), "r"(b1));
}

// ======================= 0: fused prep (init + zero out + all converts) ======
// Segments (float4 units): [0,Z4) zero out | [Z4,Z4+H4) hs | wg | wu | wd
#define Z4  (NTOK*HDIM/4)                 // 4194304
#define H4  (NTOK*HDIM/4)                 // 4194304
#define W4  (NEXP*IDIM*HDIM/4)            // 1048576
#define PREP_UNITS (Z4 + H4 + 3*W4)       // 11534336
#define PREP_BLOCKS ((PREP_UNITS + 511) / 512)
__device__ __forceinline__ void cvt4(const float* src, __half* dst, int u) {
    float4 v = ((const float4*)src)[u];
    __half2 p0 = __floats2half2_rn(v.x, v.y);
    __half2 p1 = __floats2half2_rn(v.z, v.w);
    ((uint2*)dst)[u] = make_uint2(*(uint32_t*)&p0, *(uint32_t*)&p1);
}
__global__ void __launch_bounds__(256) prep_kernel(const float* __restrict__ hs,
                                                   const float* __restrict__ wg,
                                                   const float* __restrict__ wu,
                                                   const float* __restrict__ wd,
                                                   float* __restrict__ out) {
    if (blockIdx.x == 0 && threadIdx.x < NEXP) g_cnt[threadIdx.x] = 0;
    int u0 = blockIdx.x * 512 + threadIdx.x;
#pragma unroll
    for (int r = 0; r < 2; r++) {
        int u = u0 + r*256;
        if (u < Z4) {
            ((float4*)out)[u] = make_float4(0.f, 0.f, 0.f, 0.f);
        } else if (u < Z4 + H4) {
            cvt4(hs, g_hs_h, u - Z4);
        } else if (u < Z4 + H4 + W4) {
            cvt4(wg, g_wg_h, u - Z4 - H4);
        } else if (u < Z4 + H4 + 2*W4) {
            cvt4(wu, g_wu_h, u - Z4 - H4 - W4);
        } else if (u < PREP_UNITS) {
            cvt4(wd, g_wd_h, u - Z4 - H4 - 2*W4);
        }
    }
}

// ======================= 2: router ===========================================
__global__ void __launch_bounds__(256) router_kernel(const float* __restrict__ hs,
                                                     const float* __restrict__ wr) {
    __shared__ float swr[NEXP*HDIM];
    __shared__ float sprob[8][NEXP];
    int tid = threadIdx.x;
    for (int i = tid; i < NEXP*HDIM; i += 256) swr[i] = wr[i];
    __syncthreads();

    int warp = tid >> 5, lane = tid & 31;
    int t = blockIdx.x * 8 + warp;
    const float* hrow = hs + (size_t)t * HDIM;

    float acc[NEXP];
#pragma unroll
    for (int e = 0; e < NEXP; e++) acc[e] = 0.f;
    for (int j = lane; j < HDIM; j += 32) {
        float hv = hrow[j];
#pragma unroll
        for (int e = 0; e < NEXP; e++) acc[e] = fmaf(hv, swr[e*HDIM + j], acc[e]);
    }
#pragma unroll
    for (int e = 0; e < NEXP; e++) {
#pragma unroll
        for (int o = 16; o > 0; o >>= 1) acc[e] += __shfl_xor_sync(0xffffffffu, acc[e], o);
    }

    if (lane == 0) {
        int e0 = 0; float v0 = acc[0];
#pragma unroll
        for (int e = 1; e < NEXP; e++) if (acc[e] > v0) { v0 = acc[e]; e0 = e; }
        int e1 = -1; float v1 = -1e30f;
#pragma unroll
        for (int e = 0; e < NEXP; e++) if (e != e0 && acc[e] > v1) { v1 = acc[e]; e1 = e; }

        float z  = __expf(v1 - v0);
        float p1 = z / (1.f + z);
        g_wt[2*t]     = 1.f - p1;
        g_wt[2*t + 1] = p1;

        int pos0 = atomicAdd(&g_cnt[e0], 1);
        g_list[e0*NTOK + pos0] = 2*t;
        int pos1 = atomicAdd(&g_cnt[e1], 1);
        g_list[e1*NTOK + pos1] = 2*t + 1;

        float s = 0.f, pe[NEXP];
#pragma unroll
        for (int e = 0; e < NEXP; e++) { pe[e] = __expf(acc[e] - v0); s += pe[e]; }
        float inv = 1.f / s;
#pragma unroll
        for (int e = 0; e < NEXP; e++) sprob[warp][e] = pe[e] * inv;
    }
    __syncthreads();
    if (tid < NEXP) {
        float s = 0.f;
#pragma unroll
        for (int w = 0; w < 8; w++) s += sprob[w][tid];
        g_psum[blockIdx.x*NEXP + tid] = s;
    }
}

// ======================= 3: aux loss =========================================
__global__ void aux_kernel(float* __restrict__ out, int out_size) {
    __shared__ float part[256];
    int tid = threadIdx.x;
    int e = tid & 7, c = tid >> 3;
    const int CH = RBLOCKS / 32;
    float s = 0.f;
    for (int b = c*CH; b < (c+1)*CH; b++) s += g_psum[b*NEXP + e];
    part[tid] = s;
    __syncthreads();
    if (tid < NEXP) {
        float tot = 0.f;
        for (int cc = 0; cc < 32; cc++) tot += part[cc*8 + tid];
        part[tid] = (tot / (float)NTOK) * ((float)g_cnt[tid] / (float)NSLOT) * (float)NEXP;
    }
    __syncthreads();
    if (tid == 0 && out_size > NTOK*HDIM) {
        float a = 0.f;
#pragma unroll
        for (int ee = 0; ee < NEXP; ee++) a += part[ee];
        out[(size_t)NTOK*HDIM] = a;
    }
}

// ======================= 4: gate/up GEMM (3-stage cp.async + ldmatrix) =======
// CTA 256 thr: tile 128 tokens x 64 I. Warp grid 4(row) x 2(col): 32x32 each.
// K=512, 8 chunks of 64, 3-stage pipeline, ONE barrier per chunk.
#define GU_AE  (128*LDP)
#define GU_BE  (64*LDP)
#define GU_STG (GU_AE + 2*GU_BE)
#define GU_SMEM_BYTES (3*GU_STG*2 + 1024)
__global__ void __launch_bounds__(256) gateup_mma_kernel() {
    int e   = blockIdx.z;
    int cnt = g_cnt[e];
    int p0  = blockIdx.y * 128;
    if (p0 >= cnt) return;
    int i0  = blockIdx.x * 64;

    extern __shared__ __half smem[];
    int* s_rowoff = (int*)(smem + 3*GU_STG);
    int* s_slot   = s_rowoff + 128;

    int tid = threadIdx.x, wid = tid >> 5, lane = tid & 31;
    int wr = wid & 3, wc = wid >> 2;

    if (tid < 128) {
        int p = p0 + tid;
        int cl = (p < cnt) ? p : (cnt - 1);
        int sl = g_list[e*NTOK + cl];
        s_rowoff[tid] = (sl >> 1) * HDIM;
        s_slot[tid]   = (p < cnt) ? sl : -1;
    }
    __syncthreads();
    uint32_t sbase = smem_u32(smem);

    auto load_chunk = [&](int c, int st) {
        int k0 = c * 64;
        uint32_t a_s  = sbase + st*GU_STG*2;
        uint32_t bg_s = a_s + GU_AE*2;
        uint32_t bu_s = bg_s + GU_BE*2;
#pragma unroll
        for (int it = 0; it < 4; it++) {
            int idx = tid + it*256;
            int row = idx >> 3, v = idx & 7;
            cpasync16(a_s + (row*LDP + v*8)*2, g_hs_h + s_rowoff[row] + k0 + v*8);
        }
#pragma unroll
        for (int it = 0; it < 2; it++) {
            int idx = tid + it*256;
            int row = idx >> 3, v = idx & 7;
            size_t off = ((size_t)e*IDIM + i0 + row) * HDIM + k0 + v*8;
            cpasync16(bg_s + (row*LDP + v*8)*2, g_wg_h + off);
            cpasync16(bu_s + (row*LDP + v*8)*2, g_wu_h + off);
        }
        CP_COMMIT();
    };

    float cg[2][4][4], cu[2][4][4];
#pragma unroll
    for (int m = 0; m < 2; m++)
#pragma unroll
        for (int n = 0; n < 4; n++)
#pragma unroll
            for (int q = 0; q < 4; q++) { cg[m][n][q] = 0.f; cu[m][n][q] = 0.f; }

    int lrow = lane & 7, seg = lane >> 3;
    int rowadd = (seg & 1) ? 8 : 0, coladd = (seg >= 2) ? 8 : 0;   // A form
    int browadd = (seg >= 2) ? 8 : 0, bcoladd = (seg & 1) ? 8 : 0; // B form

    load_chunk(0, 0);
    load_chunk(1, 1);
    for (int c = 0; c < 8; c++) {
        if (c < 7) CP_WAIT1(); else CP_WAIT0();
        __syncthreads();
        if (c + 2 < 8) load_chunk(c + 2, (c + 2) % 3);
        int st = c % 3;
        uint32_t a_s  = sbase + st*GU_STG*2;
        uint32_t bg_s = a_s + GU_AE*2;
        uint32_t bu_s = bg_s + GU_BE*2;
#pragma unroll
        for (int kk = 0; kk < 64; kk += 16) {
            uint32_t a[2][4], bg[2][4], bu[2][4];
#pragma unroll
            for (int m = 0; m < 2; m++) {
                int row = wr*32 + m*16 + lrow + rowadd;
                ldsm4(a[m], a_s + (row*LDP + kk + coladd)*2);
            }
#pragma unroll
            for (int j = 0; j < 2; j++) {
                int row = wc*32 + j*16 + lrow + browadd;
                ldsm4(bg[j], bg_s + (row*LDP + kk + bcoladd)*2);
                ldsm4(bu[j], bu_s + (row*LDP + kk + bcoladd)*2);
            }
#pragma unroll
            for (int n = 0; n < 4; n++) {
                int j = n >> 1, s2 = (n & 1) * 2;
#pragma unroll
                for (int m = 0; m < 2; m++) {
                    mma16816(cg[m][n], a[m][0],a[m][1],a[m][2],a[m][3], bg[j][s2], bg[j][s2+1]);
                    mma16816(cu[m][n], a[m][0],a[m][1],a[m][2],a[m][3], bu[j][s2], bu[j][s2+1]);
                }
            }
        }
    }

    // epilogue: act = silu(g)*u -> fp16 by slot
    int g_ = lane >> 2, t_ = lane & 3;
#pragma unroll
    for (int m = 0; m < 2; m++) {
#pragma unroll
        for (int half_ = 0; half_ < 2; half_++) {
            int lr = wr*32 + m*16 + g_ + half_*8;
            int slot = s_slot[lr];
            if (slot < 0) continue;
            __half* oh = g_act_h + (size_t)slot * IDIM + i0 + wc*32;
#pragma unroll
            for (int n = 0; n < 4; n++) {
                float gv0 = cg[m][n][2*half_],   uv0 = cu[m][n][2*half_];
                float gv1 = cg[m][n][2*half_+1], uv1 = cu[m][n][2*half_+1];
                float a0 = (gv0 / (1.f + __expf(-gv0))) * uv0;
                float a1 = (gv1 / (1.f + __expf(-gv1))) * uv1;
                __half2 hp = __floats2half2_rn(a0, a1);
                *(uint32_t*)(oh + n*8 + t_*2) = *(uint32_t*)&hp;
            }
        }
    }
}

// ======================= 5: down GEMM + fused combine ========================
// CTA 256 thr: tile 128 slots x 128 h. Warp grid 4x2: 32x64 each. K=1024,
// 16 chunks of 64, 3-stage pipeline. Epilogue: atomicAdd(w * val) into out.
#define DN_AE  (128*LDP)
#define DN_BE  (128*LDP)
#define DN_STG (DN_AE + DN_BE)
#define DN_SMEM_BYTES (3*DN_STG*2 + 2048)
__global__ void __launch_bounds__(256) down_mma_kernel(float* __restrict__ out) {
    int e   = blockIdx.z;
    int cnt = g_cnt[e];
    int p0  = blockIdx.y * 128;
    if (p0 >= cnt) return;
    int h0  = blockIdx.x * 128;

    extern __shared__ __half smem[];
    int*   s_rowoff = (int*)(smem + 3*DN_STG);
    int*   s_slot   = s_rowoff + 128;
    float* s_w      = (float*)(s_slot + 128);

    int tid = threadIdx.x, wid = tid >> 5, lane = tid & 31;
    int wr = wid & 3, wc = wid >> 2;

    if (tid < 128) {
        int p = p0 + tid;
        int cl = (p < cnt) ? p : (cnt - 1);
        int sl = g_list[e*NTOK + cl];
        s_rowoff[tid] = sl * IDIM;
        s_slot[tid]   = (p < cnt) ? sl : -1;
        s_w[tid]      = g_wt[sl];
    }
    __syncthreads();
    uint32_t sbase = smem_u32(smem);

    auto load_chunk = [&](int c, int st) {
        int k0 = c * 64;
        uint32_t a_s = sbase + st*DN_STG*2;
        uint32_t b_s = a_s + DN_AE*2;
#pragma unroll
        for (int it = 0; it < 4; it++) {
            int idx = tid + it*256;
            int row = idx >> 3, v = idx & 7;
            cpasync16(a_s + (row*LDP + v*8)*2, g_act_h + s_rowoff[row] + k0 + v*8);
        }
#pragma unroll
        for (int it = 0; it < 4; it++) {
            int idx = tid + it*256;
            int row = idx >> 3, v = idx & 7;
            size_t off = ((size_t)e*HDIM + h0 + row) * IDIM + k0 + v*8;
            cpasync16(b_s + (row*LDP + v*8)*2, g_wd_h + off);
        }
        CP_COMMIT();
    };

    float cd[2][8][4];
#pragma unroll
    for (int m = 0; m < 2; m++)
#pragma unroll
        for (int n = 0; n < 8; n++)
#pragma unroll
            for (int q = 0; q < 4; q++) cd[m][n][q] = 0.f;

    int lrow = lane & 7, seg = lane >> 3;
    int rowadd = (seg & 1) ? 8 : 0, coladd = (seg >= 2) ? 8 : 0;
    int browadd = (seg >= 2) ? 8 : 0, bcoladd = (seg & 1) ? 8 : 0;

    load_chunk(0, 0);
    load_chunk(1, 1);
    for (int c = 0; c < 16; c++) {
        if (c < 15) CP_WAIT1(); else CP_WAIT0();
        __syncthreads();
        if (c + 2 < 16) load_chunk(c + 2, (c + 2) % 3);
        int st = c % 3;
        uint32_t a_s = sbase + st*DN_STG*2;
        uint32_t b_s = a_s + DN_AE*2;
#pragma unroll
        for (int kk = 0; kk < 64; kk += 16) {
            uint32_t a[2][4], bb[4][4];
#pragma unroll
            for (int m = 0; m < 2; m++) {
                int row = wr*32 + m*16 + lrow + rowadd;
                ldsm4(a[m], a_s + (row*LDP + kk + coladd)*2);
            }
#pragma unroll
            for (int j = 0; j < 4; j++) {
                int row = wc*64 + j*16 + lrow + browadd;
                ldsm4(bb[j], b_s + (row*LDP + kk + bcoladd)*2);
            }
#pragma unroll
            for (int n = 0; n < 8; n++) {
                int j = n >> 1, s2 = (n & 1) * 2;
#pragma unroll
                for (int m = 0; m < 2; m++) {
                    mma16816(cd[m][n], a[m][0],a[m][1],a[m][2],a[m][3], bb[j][s2], bb[j][s2+1]);
                }
            }
        }
    }

    // epilogue: out[token] += w * val (atomic, 2 contributions per element)
    int g_ = lane >> 2, t_ = lane & 3;
#pragma unroll
    for (int m = 0; m < 2; m++) {
#pragma unroll
        for (int half_ = 0; half_ < 2; half_++) {
            int lr = wr*32 + m*16 + g_ + half_*8;
            int slot = s_slot[lr];
            if (slot < 0) continue;
            float w = s_w[lr];
            float* orow = out + (size_t)(slot >> 1) * HDIM + h0 + wc*64;
#pragma unroll
            for (int n = 0; n < 8; n++) {
                atomicAdd(orow + n*8 + t_*2,     w * cd[m][n][2*half_]);
                atomicAdd(orow + n*8 + t_*2 + 1, w * cd[m][n][2*half_+1]);
            }
        }
    }
}

// ======================= launch ==============================================
extern "C" void kernel_launch(void* const* d_in, const int* in_sizes, int n_in,
                              void* d_out, int out_size) {
    const float* hs = (const float*)d_in[0];
    const float* wr = (const float*)d_in[1];
    const float* wg = (const float*)d_in[2];
    const float* wu = (const float*)d_in[3];
    const float* wd = (const float*)d_in[4];
    float* out = (float*)d_out;

    cudaFuncSetAttribute(gateup_mma_kernel, cudaFuncAttributeMaxDynamicSharedMemorySize, GU_SMEM_BYTES);
    cudaFuncSetAttribute(down_mma_kernel,   cudaFuncAttributeMaxDynamicSharedMemorySize, DN_SMEM_BYTES);

    prep_kernel<<<PREP_BLOCKS, 256>>>(hs, wg, wu, wd, out);
    router_kernel<<<RBLOCKS, 256>>>(hs, wr);
    aux_kernel<<<1, 256>>>(out, out_size);
    gateup_mma_kernel<<<dim3(IDIM/64, NTOK/128, NEXP), 256, GU_SMEM_BYTES>>>();
    down_mma_kernel<<<dim3(HDIM/128, NTOK/128, NEXP), 256, DN_SMEM_BYTES>>>(out);
}

// round 8
// speedup vs baseline: 6.2919x; 1.0158x over previous
#include <cuda_runtime.h>
#include <cuda_fp16.h>
#include <cstdint>

#define NTOK  32768          // B*S
#define HDIM  512
#define IDIM  1024
#define NEXP  8
#define NSLOT (2*NTOK)
#define RBLOCKS (NTOK/8)
#define LDP   72             // padded smem stride (halves)
#define MAXT  520            // max token-tiles: sum_e ceil(cnt_e/128) <= 512+8

// ======================= device scratch ======================================
__device__ int   g_cnt[NEXP];        // zeroed at end of aux_tilemap for next replay
__device__ int   g_cntro[NEXP];      // snapshot used by GEMM kernels
__device__ int   g_list[NEXP*NTOK];
__device__ float g_wt[NSLOT];
__device__ float g_psum[RBLOCKS*NEXP];
__device__ int   g_tilemap[MAXT];
__device__ int   g_ntiles;
__device__ __half g_hs_h[NTOK*HDIM];
__device__ __half g_wg_h[NEXP*IDIM*HDIM];
__device__ __half g_wu_h[NEXP*IDIM*HDIM];
__device__ __half g_wd_h[NEXP*HDIM*IDIM];
__device__ __half g_act_h[67108864];          // NSLOT*IDIM

// ======================= PTX helpers =========================================
__device__ __forceinline__ uint32_t smem_u32(const void* p) {
    uint32_t a;
    asm("{ .reg .u64 t; cvta.to.shared.u64 t, %1; cvt.u32.u64 %0, t; }" : "=r"(a) : "l"(p));
    return a;
}
__device__ __forceinline__ void cpasync16(uint32_t dst, const void* src) {
    asm volatile("cp.async.cg.shared.global [%0], [%1], 16;" :: "r"(dst), "l"(src));
}
#define CP_COMMIT() asm volatile("cp.async.commit_group;" ::: "memory")
#define CP_WAIT1()  asm volatile("cp.async.wait_group 1;" ::: "memory")
#define CP_WAIT0()  asm volatile("cp.async.wait_group 0;" ::: "memory")
__device__ __forceinline__ void ldsm4(uint32_t* r, uint32_t addr) {
    asm volatile("ldmatrix.sync.aligned.m8n8.x4.shared.b16 {%0,%1,%2,%3}, [%4];"
        : "=r"(r[0]), "=r"(r[1]), "=r"(r[2]), "=r"(r[3]) : "r"(addr));
}
__device__ __forceinline__ void mma16816(float* c, uint32_t a0, uint32_t a1,
                                         uint32_t a2, uint32_t a3,
                                         uint32_t b0, uint32_t b1) {
    asm volatile(
        "mma.sync.aligned.m16n8k16.row.col.f32.f16.f16.f32 "
        "{%0,%1,%2,%3}, {%4,%5,%6,%7}, {%8,%9}, {%0,%1,%2,%3};"
        : "+f"(c[0]), "+f"(c[1]), "+f"(c[2]), "+f"(c[3])
        : "r"(a0), "r"(a1), "r"(a2), "r"(a3), "r"(b0), "r"(b1));
}

// ======================= 1: fused prep + router ==============================
// Blocks [0, PREP_BLOCKS): zero out + fp32->fp16 converts.
// Blocks [PREP_BLOCKS, PREP_BLOCKS+RBLOCKS): router (independent of prep).
#define Z4  (NTOK*HDIM/4)
#define H4  (NTOK*HDIM/4)
#define W4  (NEXP*IDIM*HDIM/4)
#define PREP_UNITS (Z4 + H4 + 3*W4)
#define PREP_BLOCKS ((PREP_UNITS + 511) / 512)
__device__ __forceinline__ void cvt4(const float* src, __half* dst, int u) {
    float4 v = ((const float4*)src)[u];
    __half2 p0 = __floats2half2_rn(v.x, v.y);
    __half2 p1 = __floats2half2_rn(v.z, v.w);
    ((uint2*)dst)[u] = make_uint2(*(uint32_t*)&p0, *(uint32_t*)&p1);
}
__global__ void __launch_bounds__(256) prep_router_kernel(
        const float* __restrict__ hs, const float* __restrict__ wr,
        const float* __restrict__ wg, const float* __restrict__ wu,
        const float* __restrict__ wd, float* __restrict__ out) {
    int tid = threadIdx.x;
    if (blockIdx.x < PREP_BLOCKS) {
        int u0 = blockIdx.x * 512 + tid;
#pragma unroll
        for (int r = 0; r < 2; r++) {
            int u = u0 + r*256;
            if (u < Z4) {
                ((float4*)out)[u] = make_float4(0.f, 0.f, 0.f, 0.f);
            } else if (u < Z4 + H4) {
                cvt4(hs, g_hs_h, u - Z4);
            } else if (u < Z4 + H4 + W4) {
                cvt4(wg, g_wg_h, u - Z4 - H4);
            } else if (u < Z4 + H4 + 2*W4) {
                cvt4(wu, g_wu_h, u - Z4 - H4 - W4);
            } else if (u < PREP_UNITS) {
                cvt4(wd, g_wd_h, u - Z4 - H4 - 2*W4);
            }
        }
        return;
    }
    // ---------------- router ----------------
    int rb = blockIdx.x - PREP_BLOCKS;
    __shared__ float swr[NEXP*HDIM];
    __shared__ float sprob[8][NEXP];
    for (int i = tid; i < NEXP*HDIM; i += 256) swr[i] = wr[i];
    __syncthreads();

    int warp = tid >> 5, lane = tid & 31;
    int t = rb * 8 + warp;
    const float* hrow = hs + (size_t)t * HDIM;

    float acc[NEXP];
#pragma unroll
    for (int e = 0; e < NEXP; e++) acc[e] = 0.f;
    for (int j = lane; j < HDIM; j += 32) {
        float hv = hrow[j];
#pragma unroll
        for (int e = 0; e < NEXP; e++) acc[e] = fmaf(hv, swr[e*HDIM + j], acc[e]);
    }
#pragma unroll
    for (int e = 0; e < NEXP; e++) {
#pragma unroll
        for (int o = 16; o > 0; o >>= 1) acc[e] += __shfl_xor_sync(0xffffffffu, acc[e], o);
    }

    if (lane == 0) {
        int e0 = 0; float v0 = acc[0];
#pragma unroll
        for (int e = 1; e < NEXP; e++) if (acc[e] > v0) { v0 = acc[e]; e0 = e; }
        int e1 = -1; float v1 = -1e30f;
#pragma unroll
        for (int e = 0; e < NEXP; e++) if (e != e0 && acc[e] > v1) { v1 = acc[e]; e1 = e; }

        float z  = __expf(v1 - v0);
        float p1 = z / (1.f + z);
        g_wt[2*t]     = 1.f - p1;
        g_wt[2*t + 1] = p1;

        int pos0 = atomicAdd(&g_cnt[e0], 1);
        g_list[e0*NTOK + pos0] = 2*t;
        int pos1 = atomicAdd(&g_cnt[e1], 1);
        g_list[e1*NTOK + pos1] = 2*t + 1;

        float s = 0.f, pe[NEXP];
#pragma unroll
        for (int e = 0; e < NEXP; e++) { pe[e] = __expf(acc[e] - v0); s += pe[e]; }
        float inv = 1.f / s;
#pragma unroll
        for (int e = 0; e < NEXP; e++) sprob[warp][e] = pe[e] * inv;
    }
    __syncthreads();
    if (tid < NEXP) {
        float s = 0.f;
#pragma unroll
        for (int w = 0; w < 8; w++) s += sprob[w][tid];
        g_psum[rb*NEXP + tid] = s;
    }
}

// ======================= 2: aux loss + tilemap + counter recycle =============
__global__ void aux_tilemap_kernel(float* __restrict__ out, int out_size) {
    __shared__ float part[256];
    __shared__ int sbase[NEXP+1];
    int tid = threadIdx.x;

    // snapshot counts, zero live counters for the next graph replay
    if (tid < NEXP) { g_cntro[tid] = g_cnt[tid]; g_cnt[tid] = 0; }
    __syncthreads();

    // aux loss (deterministic fixed-order reduction)
    int e = tid & 7, c = tid >> 3;
    const int CH = RBLOCKS / 32;
    float s = 0.f;
    for (int b = c*CH; b < (c+1)*CH; b++) s += g_psum[b*NEXP + e];
    part[tid] = s;
    __syncthreads();
    if (tid < NEXP) {
        float tot = 0.f;
        for (int cc = 0; cc < 32; cc++) tot += part[cc*8 + tid];
        part[tid] = (tot / (float)NTOK) * ((float)g_cntro[tid] / (float)NSLOT) * (float)NEXP;
    }
    __syncthreads();
    if (tid == 0) {
        if (out_size > NTOK*HDIM) {
            float a = 0.f;
#pragma unroll
            for (int ee = 0; ee < NEXP; ee++) a += part[ee];
            out[(size_t)NTOK*HDIM] = a;
        }
        int b = 0;
#pragma unroll
        for (int ee = 0; ee < NEXP; ee++) { sbase[ee] = b; b += (g_cntro[ee] + 127) >> 7; }
        sbase[NEXP] = b;
        g_ntiles = b;
    }
    __syncthreads();
#pragma unroll
    for (int ee = 0; ee < NEXP; ee++) {
        int nt = sbase[ee+1] - sbase[ee];
        for (int t = tid; t < nt; t += 256) g_tilemap[sbase[ee] + t] = (ee << 16) | t;
    }
}

// ======================= 3: gate/up GEMM (3-stage cp.async + ldmatrix) =======
#define GU_AE  (128*LDP)
#define GU_BE  (64*LDP)
#define GU_STG (GU_AE + 2*GU_BE)
#define GU_SMEM_BYTES (3*GU_STG*2 + 1024)
__global__ void __launch_bounds__(256) gateup_mma_kernel() {
    int y = blockIdx.y;
    if (y >= g_ntiles) return;
    int tm  = g_tilemap[y];
    int e   = tm >> 16;
    int p0  = (tm & 0xffff) * 128;
    int cnt = g_cntro[e];
    int i0  = blockIdx.x * 64;

    extern __shared__ __half smem[];
    int* s_rowoff = (int*)(smem + 3*GU_STG);
    int* s_slot   = s_rowoff + 128;

    int tid = threadIdx.x, wid = tid >> 5, lane = tid & 31;
    int wr = wid & 3, wc = wid >> 2;

    if (tid < 128) {
        int p = p0 + tid;
        int cl = (p < cnt) ? p : (cnt - 1);
        int sl = g_list[e*NTOK + cl];
        s_rowoff[tid] = (sl >> 1) * HDIM;
        s_slot[tid]   = (p < cnt) ? sl : -1;
    }
    __syncthreads();
    uint32_t sbase_ = smem_u32(smem);

    auto load_chunk = [&](int c, int st) {
        int k0 = c * 64;
        uint32_t a_s  = sbase_ + st*GU_STG*2;
        uint32_t bg_s = a_s + GU_AE*2;
        uint32_t bu_s = bg_s + GU_BE*2;
#pragma unroll
        for (int it = 0; it < 4; it++) {
            int idx = tid + it*256;
            int row = idx >> 3, v = idx & 7;
            cpasync16(a_s + (row*LDP + v*8)*2, g_hs_h + s_rowoff[row] + k0 + v*8);
        }
#pragma unroll
        for (int it = 0; it < 2; it++) {
            int idx = tid + it*256;
            int row = idx >> 3, v = idx & 7;
            size_t off = ((size_t)e*IDIM + i0 + row) * HDIM + k0 + v*8;
            cpasync16(bg_s + (row*LDP + v*8)*2, g_wg_h + off);
            cpasync16(bu_s + (row*LDP + v*8)*2, g_wu_h + off);
        }
        CP_COMMIT();
    };

    float cg[2][4][4], cu[2][4][4];
#pragma unroll
    for (int m = 0; m < 2; m++)
#pragma unroll
        for (int n = 0; n < 4; n++)
#pragma unroll
            for (int q = 0; q < 4; q++) { cg[m][n][q] = 0.f; cu[m][n][q] = 0.f; }

    int lrow = lane & 7, seg = lane >> 3;
    int rowadd = (seg & 1) ? 8 : 0, coladd = (seg >= 2) ? 8 : 0;   // A form
    int browadd = (seg >= 2) ? 8 : 0, bcoladd = (seg & 1) ? 8 : 0; // B form

    load_chunk(0, 0);
    load_chunk(1, 1);
    for (int c = 0; c < 8; c++) {
        if (c < 7) CP_WAIT1(); else CP_WAIT0();
        __syncthreads();
        if (c + 2 < 8) load_chunk(c + 2, (c + 2) % 3);
        int st = c % 3;
        uint32_t a_s  = sbase_ + st*GU_STG*2;
        uint32_t bg_s = a_s + GU_AE*2;
        uint32_t bu_s = bg_s + GU_BE*2;
#pragma unroll
        for (int kk = 0; kk < 64; kk += 16) {
            uint32_t a[2][4], bg[2][4], bu[2][4];
#pragma unroll
            for (int m = 0; m < 2; m++) {
                int row = wr*32 + m*16 + lrow + rowadd;
                ldsm4(a[m], a_s + (row*LDP + kk + coladd)*2);
            }
#pragma unroll
            for (int j = 0; j < 2; j++) {
                int row = wc*32 + j*16 + lrow + browadd;
                ldsm4(bg[j], bg_s + (row*LDP + kk + bcoladd)*2);
                ldsm4(bu[j], bu_s + (row*LDP + kk + bcoladd)*2);
            }
#pragma unroll
            for (int n = 0; n < 4; n++) {
                int j = n >> 1, s2 = (n & 1) * 2;
#pragma unroll
                for (int m = 0; m < 2; m++) {
                    mma16816(cg[m][n], a[m][0],a[m][1],a[m][2],a[m][3], bg[j][s2], bg[j][s2+1]);
                    mma16816(cu[m][n], a[m][0],a[m][1],a[m][2],a[m][3], bu[j][s2], bu[j][s2+1]);
                }
            }
        }
    }

    // epilogue: act = silu(g)*u -> fp16 by slot
    int g_ = lane >> 2, t_ = lane & 3;
#pragma unroll
    for (int m = 0; m < 2; m++) {
#pragma unroll
        for (int half_ = 0; half_ < 2; half_++) {
            int lr = wr*32 + m*16 + g_ + half_*8;
            int slot = s_slot[lr];
            if (slot < 0) continue;
            __half* oh = g_act_h + (size_t)slot * IDIM + i0 + wc*32;
#pragma unroll
            for (int n = 0; n < 4; n++) {
                float gv0 = cg[m][n][2*half_],   uv0 = cu[m][n][2*half_];
                float gv1 = cg[m][n][2*half_+1], uv1 = cu[m][n][2*half_+1];
                float a0 = (gv0 / (1.f + __expf(-gv0))) * uv0;
                float a1 = (gv1 / (1.f + __expf(-gv1))) * uv1;
                __half2 hp = __floats2half2_rn(a0, a1);
                *(uint32_t*)(oh + n*8 + t_*2) = *(uint32_t*)&hp;
            }
        }
    }
}

// ======================= 4: down GEMM + fused combine ========================
#define DN_AE  (128*LDP)
#define DN_BE  (128*LDP)
#define DN_STG (DN_AE + DN_BE)
#define DN_SMEM_BYTES (3*DN_STG*2 + 2048)
__global__ void __launch_bounds__(256) down_mma_kernel(float* __restrict__ out) {
    int y = blockIdx.y;
    if (y >= g_ntiles) return;
    int tm  = g_tilemap[y];
    int e   = tm >> 16;
    int p0  = (tm & 0xffff) * 128;
    int cnt = g_cntro[e];
    int h0  = blockIdx.x * 128;

    extern __shared__ __half smem[];
    int*   s_rowoff = (int*)(smem + 3*DN_STG);
    int*   s_slot   = s_rowoff + 128;
    float* s_w      = (float*)(s_slot + 128);

    int tid = threadIdx.x, wid = tid >> 5, lane = tid & 31;
    int wr = wid & 3, wc = wid >> 2;

    if (tid < 128) {
        int p = p0 + tid;
        int cl = (p < cnt) ? p : (cnt - 1);
        int sl = g_list[e*NTOK + cl];
        s_rowoff[tid] = sl * IDIM;
        s_slot[tid]   = (p < cnt) ? sl : -1;
        s_w[tid]      = g_wt[sl];
    }
    __syncthreads();
    uint32_t sbase_ = smem_u32(smem);

    auto load_chunk = [&](int c, int st) {
        int k0 = c * 64;
        uint32_t a_s = sbase_ + st*DN_STG*2;
        uint32_t b_s = a_s + DN_AE*2;
#pragma unroll
        for (int it = 0; it < 4; it++) {
            int idx = tid + it*256;
            int row = idx >> 3, v = idx & 7;
            cpasync16(a_s + (row*LDP + v*8)*2, g_act_h + s_rowoff[row] + k0 + v*8);
        }
#pragma unroll
        for (int it = 0; it < 4; it++) {
            int idx = tid + it*256;
            int row = idx >> 3, v = idx & 7;
            size_t off = ((size_t)e*HDIM + h0 + row) * IDIM + k0 + v*8;
            cpasync16(b_s + (row*LDP + v*8)*2, g_wd_h + off);
        }
        CP_COMMIT();
    };

    float cd[2][8][4];
#pragma unroll
    for (int m = 0; m < 2; m++)
#pragma unroll
        for (int n = 0; n < 8; n++)
#pragma unroll
            for (int q = 0; q < 4; q++) cd[m][n][q] = 0.f;

    int lrow = lane & 7, seg = lane >> 3;
    int rowadd = (seg & 1) ? 8 : 0, coladd = (seg >= 2) ? 8 : 0;
    int browadd = (seg >= 2) ? 8 : 0, bcoladd = (seg & 1) ? 8 : 0;

    load_chunk(0, 0);
    load_chunk(1, 1);
    for (int c = 0; c < 16; c++) {
        if (c < 15) CP_WAIT1(); else CP_WAIT0();
        __syncthreads();
        if (c + 2 < 16) load_chunk(c + 2, (c + 2) % 3);
        int st = c % 3;
        uint32_t a_s = sbase_ + st*DN_STG*2;
        uint32_t b_s = a_s + DN_AE*2;
#pragma unroll
        for (int kk = 0; kk < 64; kk += 16) {
            uint32_t a[2][4], bb[4][4];
#pragma unroll
            for (int m = 0; m < 2; m++) {
                int row = wr*32 + m*16 + lrow + rowadd;
                ldsm4(a[m], a_s + (row*LDP + kk + coladd)*2);
            }
#pragma unroll
            for (int j = 0; j < 4; j++) {
                int row = wc*64 + j*16 + lrow + browadd;
                ldsm4(bb[j], b_s + (row*LDP + kk + bcoladd)*2);
            }
#pragma unroll
            for (int n = 0; n < 8; n++) {
                int j = n >> 1, s2 = (n & 1) * 2;
#pragma unroll
                for (int m = 0; m < 2; m++) {
                    mma16816(cd[m][n], a[m][0],a[m][1],a[m][2],a[m][3], bb[j][s2], bb[j][s2+1]);
                }
            }
        }
    }

    // epilogue: out[token] += w * val (atomic, 2 contributions per element)
    int g_ = lane >> 2, t_ = lane & 3;
#pragma unroll
    for (int m = 0; m < 2; m++) {
#pragma unroll
        for (int half_ = 0; half_ < 2; half_++) {
            int lr = wr*32 + m*16 + g_ + half_*8;
            int slot = s_slot[lr];
            if (slot < 0) continue;
            float w = s_w[lr];
            float* orow = out + (size_t)(slot >> 1) * HDIM + h0 + wc*64;
#pragma unroll
            for (int n = 0; n < 8; n++) {
                atomicAdd(orow + n*8 + t_*2,     w * cd[m][n][2*half_]);
                atomicAdd(orow + n*8 + t_*2 + 1, w * cd[m][n][2*half_+1]);
            }
        }
    }
}

// ======================= launch ==============================================
extern "C" void kernel_launch(void* const* d_in, const int* in_sizes, int n_in,
                              void* d_out, int out_size) {
    const float* hs = (const float*)d_in[0];
    const float* wr = (const float*)d_in[1];
    const float* wg = (const float*)d_in[2];
    const float* wu = (const float*)d_in[3];
    const float* wd = (const float*)d_in[4];
    float* out = (float*)d_out;

    cudaFuncSetAttribute(gateup_mma_kernel, cudaFuncAttributeMaxDynamicSharedMemorySize, GU_SMEM_BYTES);
    cudaFuncSetAttribute(down_mma_kernel,   cudaFuncAttributeMaxDynamicSharedMemorySize, DN_SMEM_BYTES);

    prep_router_kernel<<<PREP_BLOCKS + RBLOCKS, 256>>>(hs, wr, wg, wu, wd, out);
    aux_tilemap_kernel<<<1, 256>>>(out, out_size);
    gateup_mma_kernel<<<dim3(IDIM/64, MAXT, 1), 256, GU_SMEM_BYTES>>>();
    down_mma_kernel<<<dim3(HDIM/128, MAXT, 1), 256, DN_SMEM_BYTES>>>(out);
}